// round 6
// baseline (speedup 1.0000x reference)
#include <cuda_runtime.h>

#define DIM 1024
#define NH 16
#define HD 64
#define BATCH 2
#define LQ 2048
#define LK 2048
#define SCALE 0.125f   // HD^-0.5, power of two: exact on TF32 values

// ---------------- scratch (allocation-free: __device__ globals) ----------------
__device__ float g_Qp[BATCH * LQ * DIM];
__device__ float g_Kp[BATCH * LK * DIM];
__device__ float g_Vp[BATCH * LK * DIM];
__device__ float g_Ao[BATCH * LQ * DIM];
// pre-rounded (TF32-in-fp32) copies of inputs
__device__ float g_qr[BATCH * LQ * DIM];
__device__ float g_kr[BATCH * LK * DIM];
__device__ float g_vr[BATCH * LK * DIM];
__device__ float g_wq[DIM * DIM];
__device__ float g_wk[DIM * DIM];
__device__ float g_wv[DIM * DIM];
__device__ float g_wo[DIM * DIM];

// ---------------- tf32 helpers ----------------
__device__ __forceinline__ unsigned f2tf(float x) {      // RNA round to tf32
    unsigned r;
    asm("cvt.rna.tf32.f32 %0, %1;" : "=r"(r) : "f"(x));
    return r;
}
__device__ __forceinline__ float rnd(float x) { return __uint_as_float(f2tf(x)); }
// operands are pre-rounded: raw bit-cast load == exact RNA value
__device__ __forceinline__ unsigned ldb(const float* p) { return __float_as_uint(*p); }

__device__ __forceinline__ void mma8(float* c, const unsigned* a, unsigned b0, unsigned b1) {
    asm volatile(
        "mma.sync.aligned.m16n8k8.row.col.f32.tf32.tf32.f32 "
        "{%0,%1,%2,%3}, {%4,%5,%6,%7}, {%8,%9}, {%0,%1,%2,%3};"
        : "+f"(c[0]), "+f"(c[1]), "+f"(c[2]), "+f"(c[3])
        : "r"(a[0]), "r"(a[1]), "r"(a[2]), "r"(a[3]), "r"(b0), "r"(b1));
}

__device__ __forceinline__ void cp16(unsigned s, const void* g) {
    asm volatile("cp.async.cg.shared.global [%0], [%1], 16;" :: "r"(s), "l"(g));
}
__device__ __forceinline__ void cp_commit() { asm volatile("cp.async.commit_group;"); }

// ---------------- pre-round kernel: y = tf32_rna(x), vectorized ----------------
__global__ __launch_bounds__(256) void round_tf32(
    const float* __restrict__ x, float* __restrict__ y, int n4)
{
    int i = blockIdx.x * blockDim.x + threadIdx.x;
    if (i < n4) {
        float4 v = ((const float4*)x)[i];
        v.x = rnd(v.x); v.y = rnd(v.y); v.z = rnd(v.z); v.w = rnd(v.w);
        ((float4*)y)[i] = v;
    }
}

// ================= GEMM: C[M,N] = A[M,K] @ W[N,K]^T + bias, tf32 tensor cores =================
// A and W must be pre-rounded to TF32. If RND, output is rounded for the next stage.
#define GBM 128
#define GBN 128
#define GBK 32
#define GSR 36
#define GEMM_SMEM ((2 * GBM * GSR + 2 * GBN * GSR) * 4)

template <bool RND>
__global__ __launch_bounds__(256) void gemm_tc(
    const float* __restrict__ A, const float* __restrict__ W,
    const float* __restrict__ bias, float* __restrict__ C,
    int M, int N, int K)
{
    extern __shared__ float sm[];
    float* As = sm;
    float* Ws = sm + 2 * GBM * GSR;
    const unsigned sAs = (unsigned)__cvta_generic_to_shared(As);
    const unsigned sWs = (unsigned)__cvta_generic_to_shared(Ws);

    const int t = threadIdx.x;
    const int lane = t & 31;
    const int wid = t >> 5;
    const int wm = (wid >> 2) * 64;
    const int wn = (wid & 3) * 32;
    const int g = lane >> 2, c4 = lane & 3;
    const int bm = blockIdx.y * GBM, bn = blockIdx.x * GBN;

    const int srow = t >> 3;
    const int scol = (t & 7) * 4;

    float acc[4][4][4];
#pragma unroll
    for (int mt = 0; mt < 4; mt++)
#pragma unroll
        for (int nt = 0; nt < 4; nt++)
#pragma unroll
            for (int i = 0; i < 4; i++) acc[mt][nt][i] = 0.f;

    auto issue = [&](int kt, int buf) {
        int k0 = kt * GBK;
#pragma unroll
        for (int r = 0; r < 4; r++) {
            int row = srow + r * 32;
            cp16(sAs + (unsigned)(buf * GBM * GSR + row * GSR + scol) * 4,
                 A + (size_t)(bm + row) * K + k0 + scol);
            cp16(sWs + (unsigned)(buf * GBN * GSR + row * GSR + scol) * 4,
                 W + (size_t)(bn + row) * K + k0 + scol);
        }
        cp_commit();
    };

    const int NT = K / GBK;
    issue(0, 0);

    for (int kt = 0; kt < NT; kt++) {
        if (kt + 1 < NT) {
            issue(kt + 1, (kt + 1) & 1);
            asm volatile("cp.async.wait_group 1;");
        } else {
            asm volatile("cp.async.wait_group 0;");
        }
        __syncthreads();

        const float* Ab = As + (kt & 1) * GBM * GSR;
        const float* Wb = Ws + (kt & 1) * GBN * GSR;

#pragma unroll
        for (int ks = 0; ks < 4; ks++) {
            unsigned af[4][4], bf[4][2];
#pragma unroll
            for (int mt = 0; mt < 4; mt++) {
                const float* p = Ab + (wm + mt * 16 + g) * GSR + ks * 8 + c4;
                af[mt][0] = ldb(p);
                af[mt][2] = ldb(p + 4);
                af[mt][1] = ldb(p + 8 * GSR);
                af[mt][3] = ldb(p + 8 * GSR + 4);
            }
#pragma unroll
            for (int nt = 0; nt < 4; nt++) {
                const float* p = Wb + (wn + nt * 8 + g) * GSR + ks * 8 + c4;
                bf[nt][0] = ldb(p);
                bf[nt][1] = ldb(p + 4);
            }
#pragma unroll
            for (int mt = 0; mt < 4; mt++)
#pragma unroll
                for (int nt = 0; nt < 4; nt++)
                    mma8(acc[mt][nt], af[mt], bf[nt][0], bf[nt][1]);
        }
        __syncthreads();
    }

#pragma unroll
    for (int mt = 0; mt < 4; mt++) {
        int row = bm + wm + mt * 16 + g;
#pragma unroll
        for (int nt = 0; nt < 4; nt++) {
            int col = bn + wn + nt * 8 + 2 * c4;
            float b0 = __ldg(&bias[col]);
            float b1 = __ldg(&bias[col + 1]);
            float v00 = acc[mt][nt][0] + b0, v01 = acc[mt][nt][1] + b1;
            float v10 = acc[mt][nt][2] + b0, v11 = acc[mt][nt][3] + b1;
            if (RND) { v00 = rnd(v00); v01 = rnd(v01); v10 = rnd(v10); v11 = rnd(v11); }
            *(float2*)&C[(size_t)row * N + col]       = make_float2(v00, v01);
            *(float2*)&C[(size_t)(row + 8) * N + col] = make_float2(v10, v11);
        }
    }
}

// ================= flash attention, tf32 tensor cores =================
// Qp/Kp/Vp pre-rounded TF32; P rounded at smem store; Ao rounded at epilogue.
#define AP 68
#define ATT_TILE (64 * AP)
#define ATT_SMEM ((4 * ATT_TILE + 128 * AP) * 4 + 2 * 64 * 4)

__global__ __launch_bounds__(256) void attn_tc(
    const float* __restrict__ Qp, const float* __restrict__ Kp,
    const float* __restrict__ Vp, const int* __restrict__ kv_mask,
    float* __restrict__ Ao)
{
    extern __shared__ float sm[];
    float* Ks  = sm;
    float* Vs  = sm + 2 * ATT_TILE;
    float* Ps  = sm + 4 * ATT_TILE;
    int*   Msm = (int*)(sm + 4 * ATT_TILE + 128 * AP);

    const unsigned sK = (unsigned)__cvta_generic_to_shared(Ks);
    const unsigned sV = (unsigned)__cvta_generic_to_shared(Vs);
    const unsigned sM = (unsigned)__cvta_generic_to_shared(Msm);

    const int t = threadIdx.x, lane = t & 31, w = t >> 5;
    const int g = lane >> 2, c4 = lane & 3;
    const int qt = blockIdx.x, h = blockIdx.y, b = blockIdx.z;

    const float* Qb = Qp + ((size_t)(b * LQ + qt * 128)) * DIM + h * HD;
    const float* Kb = Kp + (size_t)b * LK * DIM + h * HD;
    const float* Vb = Vp + (size_t)b * LK * DIM + h * HD;
    const int*   mb = kv_mask + b * LK;

    auto issue_kv = [&](int kt, int buf) {
        const float* Kg = Kb + (size_t)(kt * 64) * DIM;
        const float* Vg = Vb + (size_t)(kt * 64) * DIM;
        int d4 = (t & 15) * 4;
#pragma unroll
        for (int r = 0; r < 4; r++) {
            int row = (t >> 4) + r * 16;
            cp16(sK + (unsigned)(buf * ATT_TILE + row * AP + d4) * 4,
                 Kg + (size_t)row * DIM + d4);
            cp16(sV + (unsigned)(buf * ATT_TILE + row * AP + d4) * 4,
                 Vg + (size_t)row * DIM + d4);
        }
        if (t < 16) cp16(sM + buf * 256 + t * 16, mb + kt * 64 + t * 4);
        cp_commit();
    };

    issue_kv(0, 0);

    // stage Q (scaled by exact power of two -> stays TF32) into Ps
    {
        int d4 = (t & 15) * 4;
#pragma unroll
        for (int r = 0; r < 8; r++) {
            int row = (t >> 4) + r * 16;
            float4 v = *(const float4*)(Qb + (size_t)row * DIM + d4);
            v.x *= SCALE; v.y *= SCALE; v.z *= SCALE; v.w *= SCALE;
            *(float4*)&Ps[row * AP + d4] = v;
        }
    }
    __syncthreads();

    unsigned qf[8][4];
    {
        const float* q0 = Ps + (16 * w + g) * AP + c4;
#pragma unroll
        for (int dk = 0; dk < 8; dk++) {
            qf[dk][0] = ldb(q0 + dk * 8);
            qf[dk][2] = ldb(q0 + dk * 8 + 4);
            qf[dk][1] = ldb(q0 + 8 * AP + dk * 8);
            qf[dk][3] = ldb(q0 + 8 * AP + dk * 8 + 4);
        }
    }

    float O[8][4];
#pragma unroll
    for (int nt = 0; nt < 8; nt++)
#pragma unroll
        for (int i = 0; i < 4; i++) O[nt][i] = 0.f;
    float mr0 = -1e30f, mr1 = -1e30f, lr0 = 0.f, lr1 = 0.f;

    for (int kt = 0; kt < LK / 64; kt++) {
        if (kt + 1 < LK / 64) {
            issue_kv(kt + 1, (kt + 1) & 1);
            asm volatile("cp.async.wait_group 1;");
        } else {
            asm volatile("cp.async.wait_group 0;");
        }
        __syncthreads();

        const float* K0 = Ks + (kt & 1) * ATT_TILE;
        const float* V0 = Vs + (kt & 1) * ATT_TILE;
        const int*   Mc = Msm + (kt & 1) * 64;

        // S = Q K^T
        float S[8][4];
#pragma unroll
        for (int nt = 0; nt < 8; nt++)
#pragma unroll
            for (int i = 0; i < 4; i++) S[nt][i] = 0.f;

#pragma unroll
        for (int dk = 0; dk < 8; dk++) {
#pragma unroll
            for (int nt = 0; nt < 8; nt++) {
                const float* p = K0 + (nt * 8 + g) * AP + dk * 8 + c4;
                mma8(S[nt], qf[dk], ldb(p), ldb(p + 4));
            }
        }

        // mask
#pragma unroll
        for (int nt = 0; nt < 8; nt++) {
            if (!Mc[nt * 8 + 2 * c4])     { S[nt][0] = -1e30f; S[nt][2] = -1e30f; }
            if (!Mc[nt * 8 + 2 * c4 + 1]) { S[nt][1] = -1e30f; S[nt][3] = -1e30f; }
        }

        // online softmax
        float mx0 = -1e30f, mx1 = -1e30f;
#pragma unroll
        for (int nt = 0; nt < 8; nt++) {
            mx0 = fmaxf(mx0, fmaxf(S[nt][0], S[nt][1]));
            mx1 = fmaxf(mx1, fmaxf(S[nt][2], S[nt][3]));
        }
        mx0 = fmaxf(mx0, __shfl_xor_sync(0xffffffffu, mx0, 1));
        mx0 = fmaxf(mx0, __shfl_xor_sync(0xffffffffu, mx0, 2));
        mx1 = fmaxf(mx1, __shfl_xor_sync(0xffffffffu, mx1, 1));
        mx1 = fmaxf(mx1, __shfl_xor_sync(0xffffffffu, mx1, 2));

        float mn0 = fmaxf(mr0, mx0), mn1 = fmaxf(mr1, mx1);
        float a0 = __expf(mr0 - mn0), a1 = __expf(mr1 - mn1);
        mr0 = mn0; mr1 = mn1; lr0 *= a0; lr1 *= a1;

        float s0 = 0.f, s1 = 0.f;
#pragma unroll
        for (int nt = 0; nt < 8; nt++) {
            O[nt][0] *= a0; O[nt][1] *= a0; O[nt][2] *= a1; O[nt][3] *= a1;
            float p0 = S[nt][0] > -1e29f ? __expf(S[nt][0] - mn0) : 0.f;
            float p1 = S[nt][1] > -1e29f ? __expf(S[nt][1] - mn0) : 0.f;
            float p2 = S[nt][2] > -1e29f ? __expf(S[nt][2] - mn1) : 0.f;
            float p3 = S[nt][3] > -1e29f ? __expf(S[nt][3] - mn1) : 0.f;
            S[nt][0] = p0; S[nt][1] = p1; S[nt][2] = p2; S[nt][3] = p3;
            s0 += p0 + p1; s1 += p2 + p3;
        }
        s0 += __shfl_xor_sync(0xffffffffu, s0, 1);
        s0 += __shfl_xor_sync(0xffffffffu, s0, 2);
        s1 += __shfl_xor_sync(0xffffffffu, s1, 1);
        s1 += __shfl_xor_sync(0xffffffffu, s1, 2);
        lr0 += s0; lr1 += s1;

        // publish P (RNA-rounded here; l uses unrounded sums computed above)
        float* Pw = Ps + (16 * w) * AP;
#pragma unroll
        for (int nt = 0; nt < 8; nt++) {
            *(float2*)&Pw[g * AP + nt * 8 + 2 * c4] =
                make_float2(rnd(S[nt][0]), rnd(S[nt][1]));
            *(float2*)&Pw[(g + 8) * AP + nt * 8 + 2 * c4] =
                make_float2(rnd(S[nt][2]), rnd(S[nt][3]));
        }
        __syncwarp();

        // O += P @ V (all operands TF32-exact -> raw bit-cast loads)
#pragma unroll
        for (int kk = 0; kk < 8; kk++) {
            unsigned pa[4];
            const float* pp = Pw + g * AP + kk * 8 + c4;
            pa[0] = ldb(pp);
            pa[2] = ldb(pp + 4);
            pa[1] = ldb(pp + 8 * AP);
            pa[3] = ldb(pp + 8 * AP + 4);
            const float* vr0 = V0 + (kk * 8 + c4) * AP;
            const float* vr1 = V0 + (kk * 8 + 4 + c4) * AP;
#pragma unroll
            for (int nt = 0; nt < 8; nt++)
                mma8(O[nt], pa, ldb(vr0 + nt * 8 + g), ldb(vr1 + nt * 8 + g));
        }
        __syncthreads();
    }

    // epilogue: normalize, round for the final TF32 gemm
    float inv0 = 1.f / lr0, inv1 = 1.f / lr1;
    float* Ob = Ao + ((size_t)(b * LQ + qt * 128)) * DIM + h * HD;
    int row0 = 16 * w + g;
#pragma unroll
    for (int nt = 0; nt < 8; nt++) {
        int col = nt * 8 + 2 * c4;
        *(float2*)&Ob[(size_t)row0 * DIM + col] =
            make_float2(rnd(O[nt][0] * inv0), rnd(O[nt][1] * inv0));
        *(float2*)&Ob[(size_t)(row0 + 8) * DIM + col] =
            make_float2(rnd(O[nt][2] * inv1), rnd(O[nt][3] * inv1));
    }
}

// ---------------- launch ----------------
extern "C" void kernel_launch(void* const* d_in, const int* in_sizes, int n_in,
                              void* d_out, int out_size)
{
    const float* q       = (const float*)d_in[0];
    const float* k       = (const float*)d_in[1];
    const float* v       = (const float*)d_in[2];
    const int*   kv_mask = (const int*)d_in[3];
    const float* Wq      = (const float*)d_in[4];
    const float* bq      = (const float*)d_in[5];
    const float* Wk      = (const float*)d_in[6];
    const float* bk      = (const float*)d_in[7];
    const float* Wv      = (const float*)d_in[8];
    const float* bv      = (const float*)d_in[9];
    const float* Wo      = (const float*)d_in[10];
    const float* bo      = (const float*)d_in[11];
    float* out = (float*)d_out;

    float *Qp, *Kp, *Vp, *Ao, *qr, *kr, *vr, *wq, *wk, *wv, *wo;
    cudaGetSymbolAddress((void**)&Qp, g_Qp);
    cudaGetSymbolAddress((void**)&Kp, g_Kp);
    cudaGetSymbolAddress((void**)&Vp, g_Vp);
    cudaGetSymbolAddress((void**)&Ao, g_Ao);
    cudaGetSymbolAddress((void**)&qr, g_qr);
    cudaGetSymbolAddress((void**)&kr, g_kr);
    cudaGetSymbolAddress((void**)&vr, g_vr);
    cudaGetSymbolAddress((void**)&wq, g_wq);
    cudaGetSymbolAddress((void**)&wk, g_wk);
    cudaGetSymbolAddress((void**)&wv, g_wv);
    cudaGetSymbolAddress((void**)&wo, g_wo);

    cudaFuncSetAttribute(gemm_tc<true>,  cudaFuncAttributeMaxDynamicSharedMemorySize, GEMM_SMEM);
    cudaFuncSetAttribute(gemm_tc<false>, cudaFuncAttributeMaxDynamicSharedMemorySize, GEMM_SMEM);
    cudaFuncSetAttribute(attn_tc, cudaFuncAttributeMaxDynamicSharedMemorySize, ATT_SMEM);

    // pre-round inputs to TF32 (RNA) once
    const int ACT4 = BATCH * LQ * DIM / 4;   // 1,048,576 float4
    const int W4   = DIM * DIM / 4;          // 262,144 float4
    round_tf32<<<ACT4 / 256, 256>>>(q, qr, ACT4);
    round_tf32<<<ACT4 / 256, 256>>>(k, kr, ACT4);
    round_tf32<<<ACT4 / 256, 256>>>(v, vr, ACT4);
    round_tf32<<<W4 / 256, 256>>>(Wq, wq, W4);
    round_tf32<<<W4 / 256, 256>>>(Wk, wk, W4);
    round_tf32<<<W4 / 256, 256>>>(Wv, wv, W4);
    round_tf32<<<W4 / 256, 256>>>(Wo, wo, W4);

    dim3 ggrid(DIM / GBN, (BATCH * LQ) / GBM);  // (8, 32)
    gemm_tc<true><<<ggrid, 256, GEMM_SMEM>>>(qr, wq, bq, Qp, BATCH * LQ, DIM, DIM);
    gemm_tc<true><<<ggrid, 256, GEMM_SMEM>>>(kr, wk, bk, Kp, BATCH * LK, DIM, DIM);
    gemm_tc<true><<<ggrid, 256, GEMM_SMEM>>>(vr, wv, bv, Vp, BATCH * LK, DIM, DIM);

    attn_tc<<<dim3(LQ / 128, NH, BATCH), 256, ATT_SMEM>>>(Qp, Kp, Vp, kv_mask, Ao);

    gemm_tc<false><<<ggrid, 256, GEMM_SMEM>>>(Ao, wo, bo, out, BATCH * LQ, DIM, DIM);
}

// round 7
// speedup vs baseline: 1.3025x; 1.3025x over previous
#include <cuda_runtime.h>

#define DIM 1024
#define NH 16
#define HD 64
#define BATCH 2
#define LQ 2048
#define LK 2048
#define SCALE 0.125f   // HD^-0.5, power of two: exact on TF32 values

// ---------------- scratch (allocation-free: __device__ globals) ----------------
__device__ float g_Qp[BATCH * LQ * DIM];
__device__ float g_Kp[BATCH * LK * DIM];
__device__ float g_Vp[BATCH * LK * DIM];
__device__ float g_Ao[BATCH * LQ * DIM];
// pre-rounded (TF32-in-fp32) copies of inputs
__device__ float g_qr[BATCH * LQ * DIM];
__device__ float g_kr[BATCH * LK * DIM];
__device__ float g_vr[BATCH * LK * DIM];
__device__ float g_wq[DIM * DIM];
__device__ float g_wk[DIM * DIM];
__device__ float g_wv[DIM * DIM];
__device__ float g_wo[DIM * DIM];

// ---------------- tf32 helpers ----------------
__device__ __forceinline__ unsigned f2tf(float x) {      // RNA round to tf32
    unsigned r;
    asm("cvt.rna.tf32.f32 %0, %1;" : "=r"(r) : "f"(x));
    return r;
}
__device__ __forceinline__ float rnd(float x) { return __uint_as_float(f2tf(x)); }

__device__ __forceinline__ void mma8(float* c, const unsigned* a, unsigned b0, unsigned b1) {
    asm volatile(
        "mma.sync.aligned.m16n8k8.row.col.f32.tf32.tf32.f32 "
        "{%0,%1,%2,%3}, {%4,%5,%6,%7}, {%8,%9}, {%0,%1,%2,%3};"
        : "+f"(c[0]), "+f"(c[1]), "+f"(c[2]), "+f"(c[3])
        : "r"(a[0]), "r"(a[1]), "r"(a[2]), "r"(a[3]), "r"(b0), "r"(b1));
}

// ldmatrix x4 on fp32 data: each m8n8.b16 tile == 8x4 fp32 tile; lane l gets
// fp32 element (row l/4, col l%4) -- exactly the tf32 mma fragment layout.
__device__ __forceinline__ void ldsm4(unsigned& r0, unsigned& r1, unsigned& r2,
                                      unsigned& r3, unsigned addr) {
    asm volatile("ldmatrix.sync.aligned.m8n8.x4.shared.b16 {%0,%1,%2,%3}, [%4];"
                 : "=r"(r0), "=r"(r1), "=r"(r2), "=r"(r3) : "r"(addr));
}

__device__ __forceinline__ void cp16(unsigned s, const void* g) {
    asm volatile("cp.async.cg.shared.global [%0], [%1], 16;" :: "r"(s), "l"(g));
}
__device__ __forceinline__ void cp_commit() { asm volatile("cp.async.commit_group;"); }

// ---------------- pre-round kernels ----------------
__global__ __launch_bounds__(256) void round3(
    const float* __restrict__ a, const float* __restrict__ b, const float* __restrict__ c,
    float* __restrict__ oa, float* __restrict__ ob, float* __restrict__ oc, int n4)
{
    const float* x = blockIdx.y == 0 ? a : blockIdx.y == 1 ? b : c;
    float*       y = blockIdx.y == 0 ? oa : blockIdx.y == 1 ? ob : oc;
    int i = blockIdx.x * blockDim.x + threadIdx.x;
    if (i < n4) {
        float4 v = ((const float4*)x)[i];
        v.x = rnd(v.x); v.y = rnd(v.y); v.z = rnd(v.z); v.w = rnd(v.w);
        ((float4*)y)[i] = v;
    }
}
__global__ __launch_bounds__(256) void round4(
    const float* __restrict__ a, const float* __restrict__ b,
    const float* __restrict__ c, const float* __restrict__ d,
    float* __restrict__ oa, float* __restrict__ ob,
    float* __restrict__ oc, float* __restrict__ od, int n4)
{
    const float* x = blockIdx.y == 0 ? a : blockIdx.y == 1 ? b : blockIdx.y == 2 ? c : d;
    float*       y = blockIdx.y == 0 ? oa : blockIdx.y == 1 ? ob : blockIdx.y == 2 ? oc : od;
    int i = blockIdx.x * blockDim.x + threadIdx.x;
    if (i < n4) {
        float4 v = ((const float4*)x)[i];
        v.x = rnd(v.x); v.y = rnd(v.y); v.z = rnd(v.z); v.w = rnd(v.w);
        ((float4*)y)[i] = v;
    }
}

// ================= GEMM: C[M,N] = A[M,K] @ W[N,K]^T + bias =================
#define GBM 128
#define GBN 128
#define GBK 32
#define GSR 36      // row stride (floats): 144B = 9x16B -> LDSM conflict-free
#define GEMM_SMEM ((2 * GBM * GSR + 2 * GBN * GSR) * 4)

template <bool RND>
__global__ __launch_bounds__(256) void gemm_tc(
    const float* __restrict__ A, const float* __restrict__ W,
    const float* __restrict__ bias, float* __restrict__ C,
    int M, int N, int K)
{
    extern __shared__ float sm[];
    float* As = sm;
    float* Ws = sm + 2 * GBM * GSR;
    const unsigned sAs = (unsigned)__cvta_generic_to_shared(As);
    const unsigned sWs = (unsigned)__cvta_generic_to_shared(Ws);

    const int t = threadIdx.x;
    const int lane = t & 31;
    const int wid = t >> 5;
    const int wm = (wid >> 2) * 64;
    const int wn = (wid & 3) * 32;
    const int c4 = lane & 3;
    const int lrow = lane & 7;
    // ldmatrix lane patterns
    const int rA = ((lane >> 3) & 1) * 8 + lrow;  const int kbA = (lane >> 4) * 16;
    const int rB = (lane >> 4) * 8 + lrow;        const int kbB = ((lane >> 3) & 1) * 16;
    const int g = lane >> 2;
    const int bm = blockIdx.y * GBM, bn = blockIdx.x * GBN;

    const int srow = t >> 3;
    const int scol = (t & 7) * 4;

    float acc[4][4][4];
#pragma unroll
    for (int mt = 0; mt < 4; mt++)
#pragma unroll
        for (int nt = 0; nt < 4; nt++)
#pragma unroll
            for (int i = 0; i < 4; i++) acc[mt][nt][i] = 0.f;

    auto issue = [&](int kt, int buf) {
        int k0 = kt * GBK;
#pragma unroll
        for (int r = 0; r < 4; r++) {
            int row = srow + r * 32;
            cp16(sAs + (unsigned)(buf * GBM * GSR + row * GSR + scol) * 4,
                 A + (size_t)(bm + row) * K + k0 + scol);
            cp16(sWs + (unsigned)(buf * GBN * GSR + row * GSR + scol) * 4,
                 W + (size_t)(bn + row) * K + k0 + scol);
        }
        cp_commit();
    };

    const int NT = K / GBK;
    issue(0, 0);

    for (int kt = 0; kt < NT; kt++) {
        if (kt + 1 < NT) {
            issue(kt + 1, (kt + 1) & 1);
            asm volatile("cp.async.wait_group 1;");
        } else {
            asm volatile("cp.async.wait_group 0;");
        }
        __syncthreads();

        const unsigned abase = sAs + (unsigned)((kt & 1) * GBM * GSR + (wm + rA) * GSR) * 4 + kbA;
        const unsigned bbase = sWs + (unsigned)((kt & 1) * GBN * GSR + (wn + rB) * GSR) * 4 + kbB;

#pragma unroll
        for (int ks = 0; ks < 4; ks++) {
            unsigned af[4][4], bf[4][2];
#pragma unroll
            for (int mt = 0; mt < 4; mt++)
                ldsm4(af[mt][0], af[mt][1], af[mt][2], af[mt][3],
                      abase + (unsigned)(mt * 16 * GSR) * 4 + ks * 32);
#pragma unroll
            for (int ntp = 0; ntp < 2; ntp++)
                ldsm4(bf[2 * ntp][0], bf[2 * ntp][1], bf[2 * ntp + 1][0], bf[2 * ntp + 1][1],
                      bbase + (unsigned)(ntp * 16 * GSR) * 4 + ks * 32);
#pragma unroll
            for (int mt = 0; mt < 4; mt++)
#pragma unroll
                for (int nt = 0; nt < 4; nt++)
                    mma8(acc[mt][nt], af[mt], bf[nt][0], bf[nt][1]);
        }
        __syncthreads();
    }

#pragma unroll
    for (int mt = 0; mt < 4; mt++) {
        int row = bm + wm + mt * 16 + g;
#pragma unroll
        for (int nt = 0; nt < 4; nt++) {
            int col = bn + wn + nt * 8 + 2 * c4;
            float b0 = __ldg(&bias[col]);
            float b1 = __ldg(&bias[col + 1]);
            float v00 = acc[mt][nt][0] + b0, v01 = acc[mt][nt][1] + b1;
            float v10 = acc[mt][nt][2] + b0, v11 = acc[mt][nt][3] + b1;
            if (RND) { v00 = rnd(v00); v01 = rnd(v01); v10 = rnd(v10); v11 = rnd(v11); }
            *(float2*)&C[(size_t)row * N + col]       = make_float2(v00, v01);
            *(float2*)&C[(size_t)(row + 8) * N + col] = make_float2(v10, v11);
        }
    }
}

// ================= flash attention, tf32 + ldmatrix =================
// smem: Ks double [2][64][AP], Vs single [64][AP] (raw), Vt [64][AP] (transposed),
// Ps [128][AP] (Q staging then P), mask double.
#define AP 68       // 272B = 17x16B -> LDSM conflict-free
#define ATT_TILE (64 * AP)
#define ATT_SMEM ((384 * AP) * 4 + 2 * 64 * 4)

__global__ __launch_bounds__(256) void attn_tc(
    const float* __restrict__ Qp, const float* __restrict__ Kp,
    const float* __restrict__ Vp, const int* __restrict__ kv_mask,
    float* __restrict__ Ao)
{
    extern __shared__ float sm[];
    float* Ks  = sm;                       // 2 x [64 x AP]
    float* Vs  = sm + 2 * ATT_TILE;        // [64 x AP] raw V
    float* Vt  = Vs + ATT_TILE;            // [64 x AP] V transposed [d][kv]
    float* Ps  = Vt + ATT_TILE;            // [128 x AP]
    int*   Msm = (int*)(Ps + 128 * AP);    // 2 x 64

    const unsigned sK  = (unsigned)__cvta_generic_to_shared(Ks);
    const unsigned sV  = (unsigned)__cvta_generic_to_shared(Vs);
    const unsigned sVt = (unsigned)__cvta_generic_to_shared(Vt);
    const unsigned sP  = (unsigned)__cvta_generic_to_shared(Ps);
    const unsigned sM  = (unsigned)__cvta_generic_to_shared(Msm);

    const int t = threadIdx.x, lane = t & 31, w = t >> 5;
    const int c4 = lane & 3, g = lane >> 2;
    const int lrow = lane & 7;
    const int rA = ((lane >> 3) & 1) * 8 + lrow;  const int kbA = (lane >> 4) * 16;
    const int rB = (lane >> 4) * 8 + lrow;        const int kbB = ((lane >> 3) & 1) * 16;
    const int qt = blockIdx.x, h = blockIdx.y, b = blockIdx.z;

    const float* Qb = Qp + ((size_t)(b * LQ + qt * 128)) * DIM + h * HD;
    const float* Kb = Kp + (size_t)b * LK * DIM + h * HD;
    const float* Vb = Vp + (size_t)b * LK * DIM + h * HD;
    const int*   mb = kv_mask + b * LK;

    auto issue_kv = [&](int kt, int buf) {
        const float* Kg = Kb + (size_t)(kt * 64) * DIM;
        const float* Vg = Vb + (size_t)(kt * 64) * DIM;
        int d4 = (t & 15) * 4;
#pragma unroll
        for (int r = 0; r < 4; r++) {
            int row = (t >> 4) + r * 16;
            cp16(sK + (unsigned)(buf * ATT_TILE + row * AP + d4) * 4,
                 Kg + (size_t)row * DIM + d4);
            cp16(sV + (unsigned)(row * AP + d4) * 4,
                 Vg + (size_t)row * DIM + d4);
        }
        if (t < 16) cp16(sM + buf * 256 + t * 16, mb + kt * 64 + t * 4);
        cp_commit();
    };

    issue_kv(0, 0);

    // stage Q (x SCALE: exact power of two on TF32 values) into Ps
    {
        int d4 = (t & 15) * 4;
#pragma unroll
        for (int r = 0; r < 8; r++) {
            int row = (t >> 4) + r * 16;
            float4 v = *(const float4*)(Qb + (size_t)row * DIM + d4);
            v.x *= SCALE; v.y *= SCALE; v.z *= SCALE; v.w *= SCALE;
            *(float4*)&Ps[row * AP + d4] = v;
        }
    }
    __syncthreads();

    // Q A-fragments via ldmatrix (warp-private rows)
    unsigned qf[8][4];
    {
        unsigned qbase = sP + (unsigned)((16 * w + rA) * AP) * 4 + kbA;
#pragma unroll
        for (int dk = 0; dk < 8; dk++)
            ldsm4(qf[dk][0], qf[dk][1], qf[dk][2], qf[dk][3], qbase + dk * 32);
    }

    float O[8][4];
#pragma unroll
    for (int nt = 0; nt < 8; nt++)
#pragma unroll
        for (int i = 0; i < 4; i++) O[nt][i] = 0.f;
    float mr0 = -1e30f, mr1 = -1e30f, lr0 = 0.f, lr1 = 0.f;

    const unsigned pbase = sP + (unsigned)((16 * w + rA) * AP) * 4 + kbA;
    const unsigned vtbase = sVt + (unsigned)(rB * AP) * 4 + kbB;

    for (int kt = 0; kt < LK / 64; kt++) {
        asm volatile("cp.async.wait_group 0;");
        __syncthreads();

        // transpose Vs[kv][d] -> Vt[d][kv] (LDS.128 + 4 STS, both conflict-free)
        {
            int kv = t & 63, cgrp = t >> 6;
            const float* Vrow = Vs + kv * AP;
#pragma unroll
            for (int j = 0; j < 4; j++) {
                int d4 = cgrp + 4 * j;
                float4 x = *(const float4*)&Vrow[d4 * 4];
                Vt[(d4 * 4 + 0) * AP + kv] = x.x;
                Vt[(d4 * 4 + 1) * AP + kv] = x.y;
                Vt[(d4 * 4 + 2) * AP + kv] = x.z;
                Vt[(d4 * 4 + 3) * AP + kv] = x.w;
            }
        }
        __syncthreads();

        if (kt + 1 < LK / 64) issue_kv(kt + 1, (kt + 1) & 1);

        const int* Mc = Msm + (kt & 1) * 64;
        const unsigned kbase = sK + (unsigned)((kt & 1) * ATT_TILE + rB * AP) * 4 + kbB;

        // S = Q K^T : B-frags via ldmatrix (2 nt per LDSM)
        float S[8][4];
#pragma unroll
        for (int nt = 0; nt < 8; nt++)
#pragma unroll
            for (int i = 0; i < 4; i++) S[nt][i] = 0.f;

#pragma unroll
        for (int dk = 0; dk < 8; dk++) {
#pragma unroll
            for (int ntp = 0; ntp < 4; ntp++) {
                unsigned b0, b1, b2, b3;
                ldsm4(b0, b1, b2, b3, kbase + (unsigned)(ntp * 16 * AP) * 4 + dk * 32);
                mma8(S[2 * ntp],     qf[dk], b0, b1);
                mma8(S[2 * ntp + 1], qf[dk], b2, b3);
            }
        }

        // mask
#pragma unroll
        for (int nt = 0; nt < 8; nt++) {
            if (!Mc[nt * 8 + 2 * c4])     { S[nt][0] = -1e30f; S[nt][2] = -1e30f; }
            if (!Mc[nt * 8 + 2 * c4 + 1]) { S[nt][1] = -1e30f; S[nt][3] = -1e30f; }
        }

        // online softmax (4 lanes share a q-row)
        float mx0 = -1e30f, mx1 = -1e30f;
#pragma unroll
        for (int nt = 0; nt < 8; nt++) {
            mx0 = fmaxf(mx0, fmaxf(S[nt][0], S[nt][1]));
            mx1 = fmaxf(mx1, fmaxf(S[nt][2], S[nt][3]));
        }
        mx0 = fmaxf(mx0, __shfl_xor_sync(0xffffffffu, mx0, 1));
        mx0 = fmaxf(mx0, __shfl_xor_sync(0xffffffffu, mx0, 2));
        mx1 = fmaxf(mx1, __shfl_xor_sync(0xffffffffu, mx1, 1));
        mx1 = fmaxf(mx1, __shfl_xor_sync(0xffffffffu, mx1, 2));

        float mn0 = fmaxf(mr0, mx0), mn1 = fmaxf(mr1, mx1);
        float a0 = __expf(mr0 - mn0), a1 = __expf(mr1 - mn1);
        mr0 = mn0; mr1 = mn1; lr0 *= a0; lr1 *= a1;

        float s0 = 0.f, s1 = 0.f;
#pragma unroll
        for (int nt = 0; nt < 8; nt++) {
            O[nt][0] *= a0; O[nt][1] *= a0; O[nt][2] *= a1; O[nt][3] *= a1;
            float p0 = S[nt][0] > -1e29f ? __expf(S[nt][0] - mn0) : 0.f;
            float p1 = S[nt][1] > -1e29f ? __expf(S[nt][1] - mn0) : 0.f;
            float p2 = S[nt][2] > -1e29f ? __expf(S[nt][2] - mn1) : 0.f;
            float p3 = S[nt][3] > -1e29f ? __expf(S[nt][3] - mn1) : 0.f;
            S[nt][0] = p0; S[nt][1] = p1; S[nt][2] = p2; S[nt][3] = p3;
            s0 += p0 + p1; s1 += p2 + p3;
        }
        s0 += __shfl_xor_sync(0xffffffffu, s0, 1);
        s0 += __shfl_xor_sync(0xffffffffu, s0, 2);
        s1 += __shfl_xor_sync(0xffffffffu, s1, 1);
        s1 += __shfl_xor_sync(0xffffffffu, s1, 2);
        lr0 += s0; lr1 += s1;

        // publish P (RNA-rounded; warp-private slice)
        float* Pw = Ps + (16 * w) * AP;
#pragma unroll
        for (int nt = 0; nt < 8; nt++) {
            *(float2*)&Pw[g * AP + nt * 8 + 2 * c4] =
                make_float2(rnd(S[nt][0]), rnd(S[nt][1]));
            *(float2*)&Pw[(g + 8) * AP + nt * 8 + 2 * c4] =
                make_float2(rnd(S[nt][2]), rnd(S[nt][3]));
        }
        __syncwarp();

        // O += P @ V : A-frags (P) and B-frags (Vt) both via ldmatrix
#pragma unroll
        for (int kk = 0; kk < 8; kk++) {
            unsigned pa[4];
            ldsm4(pa[0], pa[1], pa[2], pa[3], pbase + kk * 32);
#pragma unroll
            for (int ntp = 0; ntp < 4; ntp++) {
                unsigned v0, v1, v2, v3;
                ldsm4(v0, v1, v2, v3, vtbase + (unsigned)(ntp * 16 * AP) * 4 + kk * 32);
                mma8(O[2 * ntp],     pa, v0, v1);
                mma8(O[2 * ntp + 1], pa, v2, v3);
            }
        }
    }

    // epilogue: normalize, round for the final TF32 gemm
    float inv0 = 1.f / lr0, inv1 = 1.f / lr1;
    float* Ob = Ao + ((size_t)(b * LQ + qt * 128)) * DIM + h * HD;
    int row0 = 16 * w + g;
#pragma unroll
    for (int nt = 0; nt < 8; nt++) {
        int col = nt * 8 + 2 * c4;
        *(float2*)&Ob[(size_t)row0 * DIM + col] =
            make_float2(rnd(O[nt][0] * inv0), rnd(O[nt][1] * inv0));
        *(float2*)&Ob[(size_t)(row0 + 8) * DIM + col] =
            make_float2(rnd(O[nt][2] * inv1), rnd(O[nt][3] * inv1));
    }
}

// ---------------- launch ----------------
extern "C" void kernel_launch(void* const* d_in, const int* in_sizes, int n_in,
                              void* d_out, int out_size)
{
    const float* q       = (const float*)d_in[0];
    const float* k       = (const float*)d_in[1];
    const float* v       = (const float*)d_in[2];
    const int*   kv_mask = (const int*)d_in[3];
    const float* Wq      = (const float*)d_in[4];
    const float* bq      = (const float*)d_in[5];
    const float* Wk      = (const float*)d_in[6];
    const float* bk      = (const float*)d_in[7];
    const float* Wv      = (const float*)d_in[8];
    const float* bv      = (const float*)d_in[9];
    const float* Wo      = (const float*)d_in[10];
    const float* bo      = (const float*)d_in[11];
    float* out = (float*)d_out;

    float *Qp, *Kp, *Vp, *Ao, *qr, *kr, *vr, *wq, *wk, *wv, *wo;
    cudaGetSymbolAddress((void**)&Qp, g_Qp);
    cudaGetSymbolAddress((void**)&Kp, g_Kp);
    cudaGetSymbolAddress((void**)&Vp, g_Vp);
    cudaGetSymbolAddress((void**)&Ao, g_Ao);
    cudaGetSymbolAddress((void**)&qr, g_qr);
    cudaGetSymbolAddress((void**)&kr, g_kr);
    cudaGetSymbolAddress((void**)&vr, g_vr);
    cudaGetSymbolAddress((void**)&wq, g_wq);
    cudaGetSymbolAddress((void**)&wk, g_wk);
    cudaGetSymbolAddress((void**)&wv, g_wv);
    cudaGetSymbolAddress((void**)&wo, g_wo);

    cudaFuncSetAttribute(gemm_tc<true>,  cudaFuncAttributeMaxDynamicSharedMemorySize, GEMM_SMEM);
    cudaFuncSetAttribute(gemm_tc<false>, cudaFuncAttributeMaxDynamicSharedMemorySize, GEMM_SMEM);
    cudaFuncSetAttribute(attn_tc, cudaFuncAttributeMaxDynamicSharedMemorySize, ATT_SMEM);

    const int ACT4 = BATCH * LQ * DIM / 4;
    const int W4   = DIM * DIM / 4;
    round3<<<dim3(ACT4 / 256, 3), 256>>>(q, k, v, qr, kr, vr, ACT4);
    round4<<<dim3(W4 / 256, 4), 256>>>(Wq, Wk, Wv, Wo, wq, wk, wv, wo, W4);

    dim3 ggrid(DIM / GBN, (BATCH * LQ) / GBM);  // (8, 32)
    gemm_tc<true><<<ggrid, 256, GEMM_SMEM>>>(qr, wq, bq, Qp, BATCH * LQ, DIM, DIM);
    gemm_tc<true><<<ggrid, 256, GEMM_SMEM>>>(kr, wk, bk, Kp, BATCH * LK, DIM, DIM);
    gemm_tc<true><<<ggrid, 256, GEMM_SMEM>>>(vr, wv, bv, Vp, BATCH * LK, DIM, DIM);

    attn_tc<<<dim3(LQ / 128, NH, BATCH), 256, ATT_SMEM>>>(Qp, Kp, Vp, kv_mask, Ao);

    gemm_tc<false><<<ggrid, 256, GEMM_SMEM>>>(Ao, wo, bo, out, BATCH * LQ, DIM, DIM);
}

// round 9
// speedup vs baseline: 2.2536x; 1.7301x over previous
#include <cuda_runtime.h>
#include <cuda_fp16.h>

#define DIM 1024
#define NH 16
#define HD 64
#define BATCH 2
#define LQ 2048
#define LK 2048
#define SCALE 0.125f   // HD^-0.5, power of two: exact in fp16

// ---------------- scratch (allocation-free: __device__ globals) ----------------
__device__ __half g_qh[BATCH * LQ * DIM];
__device__ __half g_kh[BATCH * LK * DIM];
__device__ __half g_vh[BATCH * LK * DIM];
__device__ __half g_wq[DIM * DIM];
__device__ __half g_wk[DIM * DIM];
__device__ __half g_wv[DIM * DIM];
__device__ __half g_wo[DIM * DIM];
__device__ __half g_Qp[BATCH * LQ * DIM];
__device__ __half g_Kp[BATCH * LK * DIM];
__device__ __half g_Vp[BATCH * LK * DIM];
__device__ __half g_Ao[BATCH * LQ * DIM];

// ---------------- mma / ldmatrix helpers ----------------
__device__ __forceinline__ void mma16(float* c, const unsigned* a, unsigned b0, unsigned b1) {
    asm volatile(
        "mma.sync.aligned.m16n8k16.row.col.f32.f16.f16.f32 "
        "{%0,%1,%2,%3}, {%4,%5,%6,%7}, {%8,%9}, {%0,%1,%2,%3};"
        : "+f"(c[0]), "+f"(c[1]), "+f"(c[2]), "+f"(c[3])
        : "r"(a[0]), "r"(a[1]), "r"(a[2]), "r"(a[3]), "r"(b0), "r"(b1));
}
__device__ __forceinline__ void ldsm4(unsigned& r0, unsigned& r1, unsigned& r2,
                                      unsigned& r3, unsigned addr) {
    asm volatile("ldmatrix.sync.aligned.m8n8.x4.shared.b16 {%0,%1,%2,%3}, [%4];"
                 : "=r"(r0), "=r"(r1), "=r"(r2), "=r"(r3) : "r"(addr));
}
__device__ __forceinline__ void ldsm4t(unsigned& r0, unsigned& r1, unsigned& r2,
                                       unsigned& r3, unsigned addr) {
    asm volatile("ldmatrix.sync.aligned.m8n8.x4.trans.shared.b16 {%0,%1,%2,%3}, [%4];"
                 : "=r"(r0), "=r"(r1), "=r"(r2), "=r"(r3) : "r"(addr));
}
__device__ __forceinline__ void cp16(unsigned s, const void* g) {
    asm volatile("cp.async.cg.shared.global [%0], [%1], 16;" :: "r"(s), "l"(g));
}
__device__ __forceinline__ void cp_commit() { asm volatile("cp.async.commit_group;"); }

// ---------------- convert kernels: f32 -> fp16 (RNE) ----------------
__global__ __launch_bounds__(256) void conv3(
    const float* __restrict__ a, const float* __restrict__ b, const float* __restrict__ c,
    __half* __restrict__ oa, __half* __restrict__ ob, __half* __restrict__ oc, int n4)
{
    const float* x = blockIdx.y == 0 ? a : blockIdx.y == 1 ? b : c;
    __half*      y = blockIdx.y == 0 ? oa : blockIdx.y == 1 ? ob : oc;
    int i = blockIdx.x * blockDim.x + threadIdx.x;
    if (i < n4) {
        float4 v = ((const float4*)x)[i];
        ((__half2*)y)[2 * i]     = __floats2half2_rn(v.x, v.y);
        ((__half2*)y)[2 * i + 1] = __floats2half2_rn(v.z, v.w);
    }
}
__global__ __launch_bounds__(256) void conv4(
    const float* __restrict__ a, const float* __restrict__ b,
    const float* __restrict__ c, const float* __restrict__ d,
    __half* __restrict__ oa, __half* __restrict__ ob,
    __half* __restrict__ oc, __half* __restrict__ od, int n4)
{
    const float* x = blockIdx.y == 0 ? a : blockIdx.y == 1 ? b : blockIdx.y == 2 ? c : d;
    __half*      y = blockIdx.y == 0 ? oa : blockIdx.y == 1 ? ob : blockIdx.y == 2 ? oc : od;
    int i = blockIdx.x * blockDim.x + threadIdx.x;
    if (i < n4) {
        float4 v = ((const float4*)x)[i];
        ((__half2*)y)[2 * i]     = __floats2half2_rn(v.x, v.y);
        ((__half2*)y)[2 * i + 1] = __floats2half2_rn(v.z, v.w);
    }
}

// ================= GEMM: C[M,N] = A[M,K] @ W[N,K]^T + bias, fp16 HMMA =================
#define GBM 128
#define GBN 128
#define GBK 64
#define HSR 72   // smem row stride in halves: 144B = 9x16B -> LDSM conflict-free
#define GEMM_SMEM (2 * (2 * GBM * HSR) * 2)   // A + W, double-buffered, bytes

template <bool HALF_OUT>
__global__ __launch_bounds__(256) void gemm_h(
    const __half* __restrict__ A, const __half* __restrict__ W,
    const float* __restrict__ bias, void* __restrict__ Cv,
    int M, int N, int K)
{
    extern __shared__ __half smh[];
    __half* As = smh;                         // 2 x [128 x 72]
    __half* Ws = smh + 2 * GBM * HSR;         // 2 x [128 x 72]
    const unsigned sAs = (unsigned)__cvta_generic_to_shared(As);
    const unsigned sWs = (unsigned)__cvta_generic_to_shared(Ws);

    const int t = threadIdx.x, lane = t & 31, wid = t >> 5;
    const int wm = (wid >> 2) * 64;           // 0 / 64
    const int wn = (wid & 3) * 32;            // 0/32/64/96
    const int c4 = lane & 3, g = lane >> 2, lrow = lane & 7;
    // ldmatrix lane patterns (offsets in halves)
    const int rA = ((lane >> 3) & 1) * 8 + lrow;  const int kA = (lane >> 4) * 8;
    const int rB = ((lane >> 4) & 1) * 8 + lrow;  const int kB = ((lane >> 3) & 1) * 8;
    const int bm = blockIdx.y * GBM, bn = blockIdx.x * GBN;

    const int srow = t >> 3;                  // staging: 32 rows/pass, 8 chunks/row
    const int scol = (t & 7) * 8;             // halves

    float acc[4][4][4];
#pragma unroll
    for (int mt = 0; mt < 4; mt++)
#pragma unroll
        for (int nt = 0; nt < 4; nt++)
#pragma unroll
            for (int i = 0; i < 4; i++) acc[mt][nt][i] = 0.f;

    auto issue = [&](int kt, int buf) {
        int k0 = kt * GBK;
#pragma unroll
        for (int r = 0; r < 4; r++) {
            int row = srow + r * 32;
            cp16(sAs + (unsigned)(buf * GBM * HSR + row * HSR + scol) * 2,
                 A + (size_t)(bm + row) * K + k0 + scol);
            cp16(sWs + (unsigned)(buf * GBN * HSR + row * HSR + scol) * 2,
                 W + (size_t)(bn + row) * K + k0 + scol);
        }
        cp_commit();
    };

    const int NT = K / GBK;   // 16
    issue(0, 0);

    for (int kt = 0; kt < NT; kt++) {
        asm volatile("cp.async.wait_group 0;");
        __syncthreads();
        if (kt + 1 < NT) issue(kt + 1, (kt + 1) & 1);

        const unsigned abase = sAs + (unsigned)((kt & 1) * GBM * HSR + (wm + rA) * HSR + kA) * 2;
        const unsigned bbase = sWs + (unsigned)((kt & 1) * GBN * HSR + (wn + rB) * HSR + kB) * 2;

#pragma unroll
        for (int ks = 0; ks < 4; ks++) {      // 4 k16-slices
            unsigned af[4][4], bf[2][4];
#pragma unroll
            for (int mt = 0; mt < 4; mt++)
                ldsm4(af[mt][0], af[mt][1], af[mt][2], af[mt][3],
                      abase + (unsigned)(mt * 16 * HSR) * 2 + ks * 32);
#pragma unroll
            for (int ntp = 0; ntp < 2; ntp++)
                ldsm4(bf[ntp][0], bf[ntp][1], bf[ntp][2], bf[ntp][3],
                      bbase + (unsigned)(ntp * 16 * HSR) * 2 + ks * 32);
#pragma unroll
            for (int mt = 0; mt < 4; mt++)
#pragma unroll
                for (int ntp = 0; ntp < 2; ntp++) {
                    mma16(acc[mt][2 * ntp],     af[mt], bf[ntp][0], bf[ntp][1]);
                    mma16(acc[mt][2 * ntp + 1], af[mt], bf[ntp][2], bf[ntp][3]);
                }
        }
    }

#pragma unroll
    for (int mt = 0; mt < 4; mt++) {
        int row = bm + wm + mt * 16 + g;
#pragma unroll
        for (int nt = 0; nt < 4; nt++) {
            int col = bn + wn + nt * 8 + 2 * c4;
            float b0 = __ldg(&bias[col]);
            float b1 = __ldg(&bias[col + 1]);
            float v00 = acc[mt][nt][0] + b0, v01 = acc[mt][nt][1] + b1;
            float v10 = acc[mt][nt][2] + b0, v11 = acc[mt][nt][3] + b1;
            if (HALF_OUT) {
                __half* C = (__half*)Cv;
                *(__half2*)&C[(size_t)row * N + col]       = __floats2half2_rn(v00, v01);
                *(__half2*)&C[(size_t)(row + 8) * N + col] = __floats2half2_rn(v10, v11);
            } else {
                float* C = (float*)Cv;
                *(float2*)&C[(size_t)row * N + col]       = make_float2(v00, v01);
                *(float2*)&C[(size_t)(row + 8) * N + col] = make_float2(v10, v11);
            }
        }
    }
}

// ================= flash attention, fp16 HMMA =================
// 256 thr = 8 warps; q-tile 128 (16 rows/warp); kv tiles 64; K,V double-buffered.
// smem (halves): Ks 2x[64x72], Vs 2x[64x72], Ps [128x72] (Q staging then P); masks.
#define KV_TILE (64 * HSR)                    // 4608 halves
#define PS_OFF  (4 * KV_TILE)                 // 18432
#define MSK_OFF ((4 * KV_TILE + 128 * HSR) * 2)   // byte offset of masks
#define ATT_SMEM (MSK_OFF + 2 * 64 * 4)

__global__ __launch_bounds__(256) void attn_h(
    const __half* __restrict__ Qp, const __half* __restrict__ Kp,
    const __half* __restrict__ Vp, const int* __restrict__ kv_mask,
    __half* __restrict__ Ao)
{
    extern __shared__ __half smh[];
    __half* Ks = smh;                         // 2 x [64 x 72]
    __half* Vs = smh + 2 * KV_TILE;           // 2 x [64 x 72]
    __half* Ps = smh + PS_OFF;                // [128 x 72]
    int*   Msm = (int*)((char*)smh + MSK_OFF);

    const unsigned sK = (unsigned)__cvta_generic_to_shared(Ks);
    const unsigned sV = (unsigned)__cvta_generic_to_shared(Vs);
    const unsigned sP = (unsigned)__cvta_generic_to_shared(Ps);
    const unsigned sM = (unsigned)__cvta_generic_to_shared(Msm);

    const int t = threadIdx.x, lane = t & 31, w = t >> 5;
    const int c4 = lane & 3, g = lane >> 2, lrow = lane & 7;
    // lane patterns (half offsets)
    const int rA = lane & 15;                     const int kA = (lane >> 4) * 8;  // A (Q/P)
    const int rB = ((lane >> 4) & 1) * 8 + lrow;  const int kB = ((lane >> 3) & 1) * 8;  // B (K)
    const int rV = ((lane >> 3) & 1) * 8 + lrow;  const int dV = (lane >> 4) * 8;  // B (V, trans)
    const int qt = blockIdx.x, h = blockIdx.y, b = blockIdx.z;

    const __half* Qb = Qp + ((size_t)(b * LQ + qt * 128)) * DIM + h * HD;
    const __half* Kb = Kp + (size_t)b * LK * DIM + h * HD;
    const __half* Vb = Vp + (size_t)b * LK * DIM + h * HD;
    const int*    mb = kv_mask + b * LK;

    auto issue_kv = [&](int kt, int buf) {
        const __half* Kg = Kb + (size_t)(kt * 64) * DIM;
        const __half* Vg = Vb + (size_t)(kt * 64) * DIM;
        int row0 = t >> 3, ch = (t & 7) * 8;
#pragma unroll
        for (int r = 0; r < 2; r++) {
            int row = row0 + r * 32;
            cp16(sK + (unsigned)(buf * KV_TILE + row * HSR + ch) * 2,
                 Kg + (size_t)row * DIM + ch);
            cp16(sV + (unsigned)(buf * KV_TILE + row * HSR + ch) * 2,
                 Vg + (size_t)row * DIM + ch);
        }
        if (t < 16) cp16(sM + buf * 256 + t * 16, mb + kt * 64 + t * 4);
        cp_commit();
    };

    issue_kv(0, 0);

    // stage Q (x SCALE, exact power of two) into Ps as fp16
    {
        const __half2 sc = __float2half2_rn(SCALE);
        int row0 = t >> 3, ch = (t & 7) * 8;
#pragma unroll
        for (int r = 0; r < 4; r++) {
            int row = row0 + r * 32;
            uint4 u = *(const uint4*)(Qb + (size_t)row * DIM + ch);
            __half2* hp = (__half2*)&u;
            hp[0] = __hmul2(hp[0], sc); hp[1] = __hmul2(hp[1], sc);
            hp[2] = __hmul2(hp[2], sc); hp[3] = __hmul2(hp[3], sc);
            *(uint4*)&Ps[row * HSR + ch] = u;
        }
    }
    __syncthreads();

    // Q A-fragments for the whole head: 4 LDSM.x4 total
    unsigned qf[4][4];
    {
        unsigned qbase = sP + (unsigned)((16 * w + rA) * HSR + kA) * 2;
#pragma unroll
        for (int ks = 0; ks < 4; ks++)
            ldsm4(qf[ks][0], qf[ks][1], qf[ks][2], qf[ks][3], qbase + ks * 32);
    }

    float O[8][4];
#pragma unroll
    for (int nt = 0; nt < 8; nt++)
#pragma unroll
        for (int i = 0; i < 4; i++) O[nt][i] = 0.f;
    float mr0 = -1e30f, mr1 = -1e30f, lr0 = 0.f, lr1 = 0.f;

    const unsigned pbase = sP + (unsigned)((16 * w + rA) * HSR + kA) * 2;

    for (int kt = 0; kt < LK / 64; kt++) {
        asm volatile("cp.async.wait_group 0;");
        __syncthreads();
        if (kt + 1 < LK / 64) issue_kv(kt + 1, (kt + 1) & 1);

        const int buf = kt & 1;
        const int* Mc = Msm + buf * 64;
        const unsigned kbase = sK + (unsigned)(buf * KV_TILE + rB * HSR + kB) * 2;
        const unsigned vbase = sV + (unsigned)(buf * KV_TILE + rV * HSR + dV) * 2;

        // S = Q K^T  (16 q x 64 kv per warp)
        float S[8][4];
#pragma unroll
        for (int nt = 0; nt < 8; nt++)
#pragma unroll
            for (int i = 0; i < 4; i++) S[nt][i] = 0.f;

#pragma unroll
        for (int ks = 0; ks < 4; ks++) {      // d = 64 -> 4 k16-slices
#pragma unroll
            for (int ntp = 0; ntp < 4; ntp++) {  // kv groups of 16
                unsigned b0, b1, b2, b3;
                ldsm4(b0, b1, b2, b3, kbase + (unsigned)(ntp * 16 * HSR) * 2 + ks * 32);
                mma16(S[2 * ntp],     qf[ks], b0, b1);
                mma16(S[2 * ntp + 1], qf[ks], b2, b3);
            }
        }

        // mask
#pragma unroll
        for (int nt = 0; nt < 8; nt++) {
            if (!Mc[nt * 8 + 2 * c4])     { S[nt][0] = -1e30f; S[nt][2] = -1e30f; }
            if (!Mc[nt * 8 + 2 * c4 + 1]) { S[nt][1] = -1e30f; S[nt][3] = -1e30f; }
        }

        // online softmax (4 lanes share a q-row)
        float mx0 = -1e30f, mx1 = -1e30f;
#pragma unroll
        for (int nt = 0; nt < 8; nt++) {
            mx0 = fmaxf(mx0, fmaxf(S[nt][0], S[nt][1]));
            mx1 = fmaxf(mx1, fmaxf(S[nt][2], S[nt][3]));
        }
        mx0 = fmaxf(mx0, __shfl_xor_sync(0xffffffffu, mx0, 1));
        mx0 = fmaxf(mx0, __shfl_xor_sync(0xffffffffu, mx0, 2));
        mx1 = fmaxf(mx1, __shfl_xor_sync(0xffffffffu, mx1, 1));
        mx1 = fmaxf(mx1, __shfl_xor_sync(0xffffffffu, mx1, 2));

        float mn0 = fmaxf(mr0, mx0), mn1 = fmaxf(mr1, mx1);
        float a0 = __expf(mr0 - mn0), a1 = __expf(mr1 - mn1);
        mr0 = mn0; mr1 = mn1; lr0 *= a0; lr1 *= a1;

        float s0 = 0.f, s1 = 0.f;
#pragma unroll
        for (int nt = 0; nt < 8; nt++) {
            O[nt][0] *= a0; O[nt][1] *= a0; O[nt][2] *= a1; O[nt][3] *= a1;
            float p0 = S[nt][0] > -1e29f ? __expf(S[nt][0] - mn0) : 0.f;
            float p1 = S[nt][1] > -1e29f ? __expf(S[nt][1] - mn0) : 0.f;
            float p2 = S[nt][2] > -1e29f ? __expf(S[nt][2] - mn1) : 0.f;
            float p3 = S[nt][3] > -1e29f ? __expf(S[nt][3] - mn1) : 0.f;
            S[nt][0] = p0; S[nt][1] = p1; S[nt][2] = p2; S[nt][3] = p3;
            s0 += p0 + p1; s1 += p2 + p3;
        }
        s0 += __shfl_xor_sync(0xffffffffu, s0, 1);
        s0 += __shfl_xor_sync(0xffffffffu, s0, 2);
        s1 += __shfl_xor_sync(0xffffffffu, s1, 1);
        s1 += __shfl_xor_sync(0xffffffffu, s1, 2);
        lr0 += s0; lr1 += s1;

        // publish P as fp16 (RNE = boundary rounding), warp-private rows
        __half* Pw = Ps + (16 * w) * HSR;
#pragma unroll
        for (int nt = 0; nt < 8; nt++) {
            *(__half2*)&Pw[g * HSR + nt * 8 + 2 * c4] =
                __floats2half2_rn(S[nt][0], S[nt][1]);
            *(__half2*)&Pw[(g + 8) * HSR + nt * 8 + 2 * c4] =
                __floats2half2_rn(S[nt][2], S[nt][3]);
        }
        __syncwarp();

        // O += P @ V : P A-frags via ldsm, V B-frags via ldsm.trans (no transpose!)
#pragma unroll
        for (int kk = 0; kk < 4; kk++) {      // kv = 64 -> 4 k16-slices
            unsigned pa[4];
            ldsm4(pa[0], pa[1], pa[2], pa[3], pbase + kk * 32);
#pragma unroll
            for (int ntp = 0; ntp < 4; ntp++) {  // d groups of 16
                unsigned v0, v1, v2, v3;
                ldsm4t(v0, v1, v2, v3,
                       vbase + (unsigned)(kk * 16 * HSR) * 2 + ntp * 32);
                mma16(O[2 * ntp],     pa, v0, v1);
                mma16(O[2 * ntp + 1], pa, v2, v3);
            }
        }
    }

    // epilogue: normalize, store fp16 for the final GEMM
    float inv0 = 1.f / lr0, inv1 = 1.f / lr1;
    __half* Ob = Ao + ((size_t)(b * LQ + qt * 128)) * DIM + h * HD;
    int row0 = 16 * w + g;
#pragma unroll
    for (int nt = 0; nt < 8; nt++) {
        int col = nt * 8 + 2 * c4;
        *(__half2*)&Ob[(size_t)row0 * DIM + col] =
            __floats2half2_rn(O[nt][0] * inv0, O[nt][1] * inv0);
        *(__half2*)&Ob[(size_t)(row0 + 8) * DIM + col] =
            __floats2half2_rn(O[nt][2] * inv1, O[nt][3] * inv1);
    }
}

// ---------------- launch ----------------
extern "C" void kernel_launch(void* const* d_in, const int* in_sizes, int n_in,
                              void* d_out, int out_size)
{
    const float* q       = (const float*)d_in[0];
    const float* k       = (const float*)d_in[1];
    const float* v       = (const float*)d_in[2];
    const int*   kv_mask = (const int*)d_in[3];
    const float* Wq      = (const float*)d_in[4];
    const float* bq      = (const float*)d_in[5];
    const float* Wk      = (const float*)d_in[6];
    const float* bk      = (const float*)d_in[7];
    const float* Wv      = (const float*)d_in[8];
    const float* bv      = (const float*)d_in[9];
    const float* Wo      = (const float*)d_in[10];
    const float* bo      = (const float*)d_in[11];
    float* out = (float*)d_out;

    __half *qh, *kh, *vh, *wq, *wk, *wv, *wo, *Qp, *Kp, *Vp, *Ao;
    cudaGetSymbolAddress((void**)&qh, g_qh);
    cudaGetSymbolAddress((void**)&kh, g_kh);
    cudaGetSymbolAddress((void**)&vh, g_vh);
    cudaGetSymbolAddress((void**)&wq, g_wq);
    cudaGetSymbolAddress((void**)&wk, g_wk);
    cudaGetSymbolAddress((void**)&wv, g_wv);
    cudaGetSymbolAddress((void**)&wo, g_wo);
    cudaGetSymbolAddress((void**)&Qp, g_Qp);
    cudaGetSymbolAddress((void**)&Kp, g_Kp);
    cudaGetSymbolAddress((void**)&Vp, g_Vp);
    cudaGetSymbolAddress((void**)&Ao, g_Ao);

    cudaFuncSetAttribute(gemm_h<true>,  cudaFuncAttributeMaxDynamicSharedMemorySize, GEMM_SMEM);
    cudaFuncSetAttribute(gemm_h<false>, cudaFuncAttributeMaxDynamicSharedMemorySize, GEMM_SMEM);
    cudaFuncSetAttribute(attn_h, cudaFuncAttributeMaxDynamicSharedMemorySize, ATT_SMEM);

    const int ACT4 = BATCH * LQ * DIM / 4;   // 1,048,576
    const int W4   = DIM * DIM / 4;          // 262,144
    conv3<<<dim3(ACT4 / 256, 3), 256>>>(q, k, v, qh, kh, vh, ACT4);
    conv4<<<dim3(W4 / 256, 4), 256>>>(Wq, Wk, Wv, Wo, wq, wk, wv, wo, W4);

    dim3 ggrid(DIM / GBN, (BATCH * LQ) / GBM);  // (8, 32)
    gemm_h<true><<<ggrid, 256, GEMM_SMEM>>>(qh, wq, bq, Qp, BATCH * LQ, DIM, DIM);
    gemm_h<true><<<ggrid, 256, GEMM_SMEM>>>(kh, wk, bk, Kp, BATCH * LK, DIM, DIM);
    gemm_h<true><<<ggrid, 256, GEMM_SMEM>>>(vh, wv, bv, Vp, BATCH * LK, DIM, DIM);

    attn_h<<<dim3(LQ / 128, NH, BATCH), 256, ATT_SMEM>>>(Qp, Kp, Vp, kv_mask, Ao);

    gemm_h<false><<<ggrid, 256, GEMM_SMEM>>>(Ao, wo, bo, out, BATCH * LQ, DIM, DIM);
}

// round 11
// speedup vs baseline: 2.4385x; 1.0821x over previous
#include <cuda_runtime.h>
#include <cuda_fp16.h>

#define DIM 1024
#define NH 16
#define HD 64
#define BATCH 2
#define LQ 2048
#define LK 2048
#define SCALE 0.125f   // HD^-0.5, power of two: exact in fp16

// ---------------- scratch (allocation-free: __device__ globals) ----------------
__device__ __half g_qh[BATCH * LQ * DIM];
__device__ __half g_kh[BATCH * LK * DIM];
__device__ __half g_vh[BATCH * LK * DIM];
__device__ __half g_wq[DIM * DIM];
__device__ __half g_wk[DIM * DIM];
__device__ __half g_wv[DIM * DIM];
__device__ __half g_wo[DIM * DIM];
__device__ __half g_Qp[BATCH * LQ * DIM];
__device__ __half g_Kp[BATCH * LK * DIM];
__device__ __half g_Vp[BATCH * LK * DIM];
__device__ __half g_Ao[BATCH * LQ * DIM];

// ---------------- mma / ldmatrix helpers ----------------
__device__ __forceinline__ void mma16(float* c, const unsigned* a, unsigned b0, unsigned b1) {
    asm volatile(
        "mma.sync.aligned.m16n8k16.row.col.f32.f16.f16.f32 "
        "{%0,%1,%2,%3}, {%4,%5,%6,%7}, {%8,%9}, {%0,%1,%2,%3};"
        : "+f"(c[0]), "+f"(c[1]), "+f"(c[2]), "+f"(c[3])
        : "r"(a[0]), "r"(a[1]), "r"(a[2]), "r"(a[3]), "r"(b0), "r"(b1));
}
__device__ __forceinline__ void ldsm4(unsigned& r0, unsigned& r1, unsigned& r2,
                                      unsigned& r3, unsigned addr) {
    asm volatile("ldmatrix.sync.aligned.m8n8.x4.shared.b16 {%0,%1,%2,%3}, [%4];"
                 : "=r"(r0), "=r"(r1), "=r"(r2), "=r"(r3) : "r"(addr));
}
__device__ __forceinline__ void ldsm4t(unsigned& r0, unsigned& r1, unsigned& r2,
                                       unsigned& r3, unsigned addr) {
    asm volatile("ldmatrix.sync.aligned.m8n8.x4.trans.shared.b16 {%0,%1,%2,%3}, [%4];"
                 : "=r"(r0), "=r"(r1), "=r"(r2), "=r"(r3) : "r"(addr));
}
__device__ __forceinline__ void cp16(unsigned s, const void* g) {
    asm volatile("cp.async.cg.shared.global [%0], [%1], 16;" :: "r"(s), "l"(g));
}
__device__ __forceinline__ void cp_commit() { asm volatile("cp.async.commit_group;"); }

// ---------------- convert kernels: f32 -> fp16 (RNE) ----------------
__global__ __launch_bounds__(256) void conv3(
    const float* __restrict__ a, const float* __restrict__ b, const float* __restrict__ c,
    __half* __restrict__ oa, __half* __restrict__ ob, __half* __restrict__ oc, int n4)
{
    const float* x = blockIdx.y == 0 ? a : blockIdx.y == 1 ? b : c;
    __half*      y = blockIdx.y == 0 ? oa : blockIdx.y == 1 ? ob : oc;
    int i = blockIdx.x * blockDim.x + threadIdx.x;
    if (i < n4) {
        float4 v = ((const float4*)x)[i];
        ((__half2*)y)[2 * i]     = __floats2half2_rn(v.x, v.y);
        ((__half2*)y)[2 * i + 1] = __floats2half2_rn(v.z, v.w);
    }
}
__global__ __launch_bounds__(256) void conv4(
    const float* __restrict__ a, const float* __restrict__ b,
    const float* __restrict__ c, const float* __restrict__ d,
    __half* __restrict__ oa, __half* __restrict__ ob,
    __half* __restrict__ oc, __half* __restrict__ od, int n4)
{
    const float* x = blockIdx.y == 0 ? a : blockIdx.y == 1 ? b : blockIdx.y == 2 ? c : d;
    __half*      y = blockIdx.y == 0 ? oa : blockIdx.y == 1 ? ob : blockIdx.y == 2 ? oc : od;
    int i = blockIdx.x * blockDim.x + threadIdx.x;
    if (i < n4) {
        float4 v = ((const float4*)x)[i];
        ((__half2*)y)[2 * i]     = __floats2half2_rn(v.x, v.y);
        ((__half2*)y)[2 * i + 1] = __floats2half2_rn(v.z, v.w);
    }
}

// ================= GEMM: C[M,N] = A[M,K] @ W[N,K]^T + bias, fp16 HMMA =================
// blockIdx.z selects one of up to 3 merged problems (QKV fused into one launch).
#define GBM 128
#define GBN 128
#define GBK 64
#define HSR 72   // smem row stride in halves: 144B = 9x16B -> LDSM conflict-free
#define GEMM_SMEM (2 * (2 * GBM * HSR) * 2)

template <bool HALF_OUT>
__global__ __launch_bounds__(256) void gemm_h(
    const __half* __restrict__ A0, const __half* __restrict__ A1,
    const __half* __restrict__ A2,
    const __half* __restrict__ W0, const __half* __restrict__ W1,
    const __half* __restrict__ W2,
    const float* __restrict__ B0, const float* __restrict__ B1,
    const float* __restrict__ B2,
    void* __restrict__ C0, void* __restrict__ C1, void* __restrict__ C2)
{
    extern __shared__ __half smh[];
    __half* As = smh;
    __half* Ws = smh + 2 * GBM * HSR;
    const unsigned sAs = (unsigned)__cvta_generic_to_shared(As);
    const unsigned sWs = (unsigned)__cvta_generic_to_shared(Ws);

    const int z = blockIdx.z;
    const __half* A  = z == 0 ? A0 : z == 1 ? A1 : A2;
    const __half* W  = z == 0 ? W0 : z == 1 ? W1 : W2;
    const float* bias = z == 0 ? B0 : z == 1 ? B1 : B2;
    void* Cv = z == 0 ? C0 : z == 1 ? C1 : C2;

    const int t = threadIdx.x, lane = t & 31, wid = t >> 5;
    const int wm = (wid >> 2) * 64;
    const int wn = (wid & 3) * 32;
    const int c4 = lane & 3, g = lane >> 2, lrow = lane & 7;
    const int rA = ((lane >> 3) & 1) * 8 + lrow;  const int kA = (lane >> 4) * 8;
    const int rB = ((lane >> 4) & 1) * 8 + lrow;  const int kB = ((lane >> 3) & 1) * 8;
    const int bm = blockIdx.y * GBM, bn = blockIdx.x * GBN;

    const int srow = t >> 3;
    const int scol = (t & 7) * 8;

    float acc[4][4][4];
#pragma unroll
    for (int mt = 0; mt < 4; mt++)
#pragma unroll
        for (int nt = 0; nt < 4; nt++)
#pragma unroll
            for (int i = 0; i < 4; i++) acc[mt][nt][i] = 0.f;

    auto issue = [&](int kt, int buf) {
        int k0 = kt * GBK;
#pragma unroll
        for (int r = 0; r < 4; r++) {
            int row = srow + r * 32;
            cp16(sAs + (unsigned)(buf * GBM * HSR + row * HSR + scol) * 2,
                 A + (size_t)(bm + row) * DIM + k0 + scol);
            cp16(sWs + (unsigned)(buf * GBN * HSR + row * HSR + scol) * 2,
                 W + (size_t)(bn + row) * DIM + k0 + scol);
        }
        cp_commit();
    };

    const int NT = DIM / GBK;   // 16
    issue(0, 0);

    for (int kt = 0; kt < NT; kt++) {
        asm volatile("cp.async.wait_group 0;");
        __syncthreads();
        if (kt + 1 < NT) issue(kt + 1, (kt + 1) & 1);

        const unsigned abase = sAs + (unsigned)((kt & 1) * GBM * HSR + (wm + rA) * HSR + kA) * 2;
        const unsigned bbase = sWs + (unsigned)((kt & 1) * GBN * HSR + (wn + rB) * HSR + kB) * 2;

#pragma unroll
        for (int ks = 0; ks < 4; ks++) {
            unsigned af[4][4], bf[2][4];
#pragma unroll
            for (int mt = 0; mt < 4; mt++)
                ldsm4(af[mt][0], af[mt][1], af[mt][2], af[mt][3],
                      abase + (unsigned)(mt * 16 * HSR) * 2 + ks * 32);
#pragma unroll
            for (int ntp = 0; ntp < 2; ntp++)
                ldsm4(bf[ntp][0], bf[ntp][1], bf[ntp][2], bf[ntp][3],
                      bbase + (unsigned)(ntp * 16 * HSR) * 2 + ks * 32);
#pragma unroll
            for (int mt = 0; mt < 4; mt++)
#pragma unroll
                for (int ntp = 0; ntp < 2; ntp++) {
                    mma16(acc[mt][2 * ntp],     af[mt], bf[ntp][0], bf[ntp][1]);
                    mma16(acc[mt][2 * ntp + 1], af[mt], bf[ntp][2], bf[ntp][3]);
                }
        }
    }

#pragma unroll
    for (int mt = 0; mt < 4; mt++) {
        int row = bm + wm + mt * 16 + g;
#pragma unroll
        for (int nt = 0; nt < 4; nt++) {
            int col = bn + wn + nt * 8 + 2 * c4;
            float b0 = __ldg(&bias[col]);
            float b1 = __ldg(&bias[col + 1]);
            float v00 = acc[mt][nt][0] + b0, v01 = acc[mt][nt][1] + b1;
            float v10 = acc[mt][nt][2] + b0, v11 = acc[mt][nt][3] + b1;
            if (HALF_OUT) {
                __half* C = (__half*)Cv;
                *(__half2*)&C[(size_t)row * DIM + col]       = __floats2half2_rn(v00, v01);
                *(__half2*)&C[(size_t)(row + 8) * DIM + col] = __floats2half2_rn(v10, v11);
            } else {
                float* C = (float*)Cv;
                *(float2*)&C[(size_t)row * DIM + col]       = make_float2(v00, v01);
                *(float2*)&C[(size_t)(row + 8) * DIM + col] = make_float2(v10, v11);
            }
        }
    }
}

// ================= flash attention, fp16 HMMA, register-resident P =================
// 256 thr = 8 warps; q-tile 128 (16 rows/warp); kv tiles 64; K,V double-buffered.
// FA2 trick: S C-fragments are re-packed in registers as PV A-fragments
// (no smem round-trip for P).
#define KV_TILE (64 * HSR)
#define PS_OFF  (4 * KV_TILE)
#define MSK_OFF ((4 * KV_TILE + 128 * HSR) * 2)
#define ATT_SMEM (MSK_OFF + 2 * 64 * 4)

__global__ __launch_bounds__(256) void attn_h(
    const __half* __restrict__ Qp, const __half* __restrict__ Kp,
    const __half* __restrict__ Vp, const int* __restrict__ kv_mask,
    __half* __restrict__ Ao)
{
    extern __shared__ __half smh[];
    __half* Ks = smh;                         // 2 x [64 x 72]
    __half* Vs = smh + 2 * KV_TILE;           // 2 x [64 x 72]
    __half* Ps = smh + PS_OFF;                // [128 x 72] (Q staging only)
    int*   Msm = (int*)((char*)smh + MSK_OFF);

    const unsigned sK = (unsigned)__cvta_generic_to_shared(Ks);
    const unsigned sV = (unsigned)__cvta_generic_to_shared(Vs);
    const unsigned sP = (unsigned)__cvta_generic_to_shared(Ps);
    const unsigned sM = (unsigned)__cvta_generic_to_shared(Msm);

    const int t = threadIdx.x, lane = t & 31, w = t >> 5;
    const int c4 = lane & 3, g = lane >> 2, lrow = lane & 7;
    const int rA = lane & 15;                     const int kA = (lane >> 4) * 8;  // A (Q)
    const int rB = ((lane >> 4) & 1) * 8 + lrow;  const int kB = ((lane >> 3) & 1) * 8;  // B (K)
    const int rV = ((lane >> 3) & 1) * 8 + lrow;  const int dV = (lane >> 4) * 8;  // B (V, trans)
    const int qt = blockIdx.x, h = blockIdx.y, b = blockIdx.z;

    const __half* Qb = Qp + ((size_t)(b * LQ + qt * 128)) * DIM + h * HD;
    const __half* Kb = Kp + (size_t)b * LK * DIM + h * HD;
    const __half* Vb = Vp + (size_t)b * LK * DIM + h * HD;
    const int*    mb = kv_mask + b * LK;

    auto issue_kv = [&](int kt, int buf) {
        const __half* Kg = Kb + (size_t)(kt * 64) * DIM;
        const __half* Vg = Vb + (size_t)(kt * 64) * DIM;
        int row0 = t >> 3, ch = (t & 7) * 8;
#pragma unroll
        for (int r = 0; r < 2; r++) {
            int row = row0 + r * 32;
            cp16(sK + (unsigned)(buf * KV_TILE + row * HSR + ch) * 2,
                 Kg + (size_t)row * DIM + ch);
            cp16(sV + (unsigned)(buf * KV_TILE + row * HSR + ch) * 2,
                 Vg + (size_t)row * DIM + ch);
        }
        if (t < 16) cp16(sM + buf * 256 + t * 16, mb + kt * 64 + t * 4);
        cp_commit();
    };

    issue_kv(0, 0);

    // stage Q (x SCALE, exact power of two) into Ps as fp16
    {
        const __half2 sc = __float2half2_rn(SCALE);
        int row0 = t >> 3, ch = (t & 7) * 8;
#pragma unroll
        for (int r = 0; r < 4; r++) {
            int row = row0 + r * 32;
            uint4 u = *(const uint4*)(Qb + (size_t)row * DIM + ch);
            __half2* hp = (__half2*)&u;
            hp[0] = __hmul2(hp[0], sc); hp[1] = __hmul2(hp[1], sc);
            hp[2] = __hmul2(hp[2], sc); hp[3] = __hmul2(hp[3], sc);
            *(uint4*)&Ps[row * HSR + ch] = u;
        }
    }
    __syncthreads();

    // Q A-fragments for the whole head: 4 LDSM.x4 total
    unsigned qf[4][4];
    {
        unsigned qbase = sP + (unsigned)((16 * w + rA) * HSR + kA) * 2;
#pragma unroll
        for (int ks = 0; ks < 4; ks++)
            ldsm4(qf[ks][0], qf[ks][1], qf[ks][2], qf[ks][3], qbase + ks * 32);
    }

    float O[8][4];
#pragma unroll
    for (int nt = 0; nt < 8; nt++)
#pragma unroll
        for (int i = 0; i < 4; i++) O[nt][i] = 0.f;
    float mr0 = -1e30f, mr1 = -1e30f, lr0 = 0.f, lr1 = 0.f;

    for (int kt = 0; kt < LK / 64; kt++) {
        asm volatile("cp.async.wait_group 0;");
        __syncthreads();
        if (kt + 1 < LK / 64) issue_kv(kt + 1, (kt + 1) & 1);

        const int buf = kt & 1;
        const int* Mc = Msm + buf * 64;
        const unsigned kbase = sK + (unsigned)(buf * KV_TILE + rB * HSR + kB) * 2;
        const unsigned vbase = sV + (unsigned)(buf * KV_TILE + rV * HSR + dV) * 2;

        // S = Q K^T  (16 q x 64 kv per warp)
        float S[8][4];
#pragma unroll
        for (int nt = 0; nt < 8; nt++)
#pragma unroll
            for (int i = 0; i < 4; i++) S[nt][i] = 0.f;

#pragma unroll
        for (int ks = 0; ks < 4; ks++) {
#pragma unroll
            for (int ntp = 0; ntp < 4; ntp++) {
                unsigned b0, b1, b2, b3;
                ldsm4(b0, b1, b2, b3, kbase + (unsigned)(ntp * 16 * HSR) * 2 + ks * 32);
                mma16(S[2 * ntp],     qf[ks], b0, b1);
                mma16(S[2 * ntp + 1], qf[ks], b2, b3);
            }
        }

        // mask
#pragma unroll
        for (int nt = 0; nt < 8; nt++) {
            if (!Mc[nt * 8 + 2 * c4])     { S[nt][0] = -1e30f; S[nt][2] = -1e30f; }
            if (!Mc[nt * 8 + 2 * c4 + 1]) { S[nt][1] = -1e30f; S[nt][3] = -1e30f; }
        }

        // online softmax (4 lanes share a q-row)
        float mx0 = -1e30f, mx1 = -1e30f;
#pragma unroll
        for (int nt = 0; nt < 8; nt++) {
            mx0 = fmaxf(mx0, fmaxf(S[nt][0], S[nt][1]));
            mx1 = fmaxf(mx1, fmaxf(S[nt][2], S[nt][3]));
        }
        mx0 = fmaxf(mx0, __shfl_xor_sync(0xffffffffu, mx0, 1));
        mx0 = fmaxf(mx0, __shfl_xor_sync(0xffffffffu, mx0, 2));
        mx1 = fmaxf(mx1, __shfl_xor_sync(0xffffffffu, mx1, 1));
        mx1 = fmaxf(mx1, __shfl_xor_sync(0xffffffffu, mx1, 2));

        float mn0 = fmaxf(mr0, mx0), mn1 = fmaxf(mr1, mx1);
        float a0 = __expf(mr0 - mn0), a1 = __expf(mr1 - mn1);
        mr0 = mn0; mr1 = mn1; lr0 *= a0; lr1 *= a1;

        float s0 = 0.f, s1 = 0.f;
#pragma unroll
        for (int nt = 0; nt < 8; nt++) {
            O[nt][0] *= a0; O[nt][1] *= a0; O[nt][2] *= a1; O[nt][3] *= a1;
            float p0 = S[nt][0] > -1e29f ? __expf(S[nt][0] - mn0) : 0.f;
            float p1 = S[nt][1] > -1e29f ? __expf(S[nt][1] - mn0) : 0.f;
            float p2 = S[nt][2] > -1e29f ? __expf(S[nt][2] - mn1) : 0.f;
            float p3 = S[nt][3] > -1e29f ? __expf(S[nt][3] - mn1) : 0.f;
            S[nt][0] = p0; S[nt][1] = p1; S[nt][2] = p2; S[nt][3] = p3;
            s0 += p0 + p1; s1 += p2 + p3;
        }
        s0 += __shfl_xor_sync(0xffffffffu, s0, 1);
        s0 += __shfl_xor_sync(0xffffffffu, s0, 2);
        s1 += __shfl_xor_sync(0xffffffffu, s1, 1);
        s1 += __shfl_xor_sync(0xffffffffu, s1, 2);
        lr0 += s0; lr1 += s1;

        // O += P @ V : P stays in registers.
        // C-frag of S == A-frag of P: for k16 slice kk, {a0,a1,a2,a3} =
        // (g, kv 16kk+2c4..), (g+8, same), (g, kv 16kk+8+2c4..), (g+8, same)
        //  = S[2kk][0,1] | S[2kk][2,3] | S[2kk+1][0,1] | S[2kk+1][2,3] as half2.
#pragma unroll
        for (int kk = 0; kk < 4; kk++) {
            unsigned pa[4];
            __half2 h0 = __floats2half2_rn(S[2 * kk][0],     S[2 * kk][1]);
            __half2 h1 = __floats2half2_rn(S[2 * kk][2],     S[2 * kk][3]);
            __half2 h2 = __floats2half2_rn(S[2 * kk + 1][0], S[2 * kk + 1][1]);
            __half2 h3 = __floats2half2_rn(S[2 * kk + 1][2], S[2 * kk + 1][3]);
            pa[0] = *(unsigned*)&h0; pa[1] = *(unsigned*)&h1;
            pa[2] = *(unsigned*)&h2; pa[3] = *(unsigned*)&h3;
#pragma unroll
            for (int ntp = 0; ntp < 4; ntp++) {
                unsigned v0, v1, v2, v3;
                ldsm4t(v0, v1, v2, v3,
                       vbase + (unsigned)(kk * 16 * HSR) * 2 + ntp * 32);
                mma16(O[2 * ntp],     pa, v0, v1);
                mma16(O[2 * ntp + 1], pa, v2, v3);
            }
        }
    }

    // epilogue: normalize, store fp16 for the final GEMM
    float inv0 = 1.f / lr0, inv1 = 1.f / lr1;
    __half* Ob = Ao + ((size_t)(b * LQ + qt * 128)) * DIM + h * HD;
    int row0 = 16 * w + g;
#pragma unroll
    for (int nt = 0; nt < 8; nt++) {
        int col = nt * 8 + 2 * c4;
        *(__half2*)&Ob[(size_t)row0 * DIM + col] =
            __floats2half2_rn(O[nt][0] * inv0, O[nt][1] * inv0);
        *(__half2*)&Ob[(size_t)(row0 + 8) * DIM + col] =
            __floats2half2_rn(O[nt][2] * inv1, O[nt][3] * inv1);
    }
}

// ---------------- launch ----------------
extern "C" void kernel_launch(void* const* d_in, const int* in_sizes, int n_in,
                              void* d_out, int out_size)
{
    const float* q       = (const float*)d_in[0];
    const float* k       = (const float*)d_in[1];
    const float* v       = (const float*)d_in[2];
    const int*   kv_mask = (const int*)d_in[3];
    const float* Wq      = (const float*)d_in[4];
    const float* bq      = (const float*)d_in[5];
    const float* Wk      = (const float*)d_in[6];
    const float* bk      = (const float*)d_in[7];
    const float* Wv      = (const float*)d_in[8];
    const float* bv      = (const float*)d_in[9];
    const float* Wo      = (const float*)d_in[10];
    const float* bo      = (const float*)d_in[11];
    float* out = (float*)d_out;

    __half *qh, *kh, *vh, *wq, *wk, *wv, *wo, *Qp, *Kp, *Vp, *Ao;
    cudaGetSymbolAddress((void**)&qh, g_qh);
    cudaGetSymbolAddress((void**)&kh, g_kh);
    cudaGetSymbolAddress((void**)&vh, g_vh);
    cudaGetSymbolAddress((void**)&wq, g_wq);
    cudaGetSymbolAddress((void**)&wk, g_wk);
    cudaGetSymbolAddress((void**)&wv, g_wv);
    cudaGetSymbolAddress((void**)&wo, g_wo);
    cudaGetSymbolAddress((void**)&Qp, g_Qp);
    cudaGetSymbolAddress((void**)&Kp, g_Kp);
    cudaGetSymbolAddress((void**)&Vp, g_Vp);
    cudaGetSymbolAddress((void**)&Ao, g_Ao);

    cudaFuncSetAttribute(gemm_h<true>,  cudaFuncAttributeMaxDynamicSharedMemorySize, GEMM_SMEM);
    cudaFuncSetAttribute(gemm_h<false>, cudaFuncAttributeMaxDynamicSharedMemorySize, GEMM_SMEM);
    cudaFuncSetAttribute(attn_h, cudaFuncAttributeMaxDynamicSharedMemorySize, ATT_SMEM);

    const int ACT4 = BATCH * LQ * DIM / 4;
    const int W4   = DIM * DIM / 4;
    conv3<<<dim3(ACT4 / 256, 3), 256>>>(q, k, v, qh, kh, vh, ACT4);
    conv4<<<dim3(W4 / 256, 4), 256>>>(Wq, Wk, Wv, Wo, wq, wk, wv, wo, W4);

    // merged Q/K/V projections in one launch (768 CTAs = 2.6 waves)
    gemm_h<true><<<dim3(DIM / GBN, (BATCH * LQ) / GBM, 3), 256, GEMM_SMEM>>>(
        qh, kh, vh, wq, wk, wv, bq, bk, bv, Qp, Kp, Vp);

    attn_h<<<dim3(LQ / 128, NH, BATCH), 256, ATT_SMEM>>>(Qp, Kp, Vp, kv_mask, Ao);

    // output projection, fp32 out
    gemm_h<false><<<dim3(DIM / GBN, (BATCH * LQ) / GBM, 1), 256, GEMM_SMEM>>>(
        Ao, Ao, Ao, wo, wo, wo, bo, bo, bo, out, out, out);
}

// round 12
// speedup vs baseline: 2.6088x; 1.0698x over previous
#include <cuda_runtime.h>
#include <cuda_fp16.h>

#define DIM 1024
#define NH 16
#define HD 64
#define BATCH 2
#define LQ 2048
#define LK 2048
// SCALE * log2(e): folded into the Q projection epilogue (fp32, pre-rounding)
#define QSCALE 0.18033688011112042f

// ---------------- scratch (allocation-free: __device__ globals) ----------------
__device__ __half g_qh[BATCH * LQ * DIM];
__device__ __half g_kh[BATCH * LK * DIM];
__device__ __half g_vh[BATCH * LK * DIM];
__device__ __half g_wq[DIM * DIM];
__device__ __half g_wk[DIM * DIM];
__device__ __half g_wv[DIM * DIM];
__device__ __half g_wo[DIM * DIM];
__device__ __half g_Qp[BATCH * LQ * DIM];
__device__ __half g_Kp[BATCH * LK * DIM];
__device__ __half g_Vp[BATCH * LK * DIM];
__device__ __half g_Ao[BATCH * LQ * DIM];

// ---------------- helpers ----------------
__device__ __forceinline__ float ex2(float x) {
    float y;
    asm("ex2.approx.ftz.f32 %0, %1;" : "=f"(y) : "f"(x));
    return y;
}
__device__ __forceinline__ void mma16(float* c, const unsigned* a, unsigned b0, unsigned b1) {
    asm volatile(
        "mma.sync.aligned.m16n8k16.row.col.f32.f16.f16.f32 "
        "{%0,%1,%2,%3}, {%4,%5,%6,%7}, {%8,%9}, {%0,%1,%2,%3};"
        : "+f"(c[0]), "+f"(c[1]), "+f"(c[2]), "+f"(c[3])
        : "r"(a[0]), "r"(a[1]), "r"(a[2]), "r"(a[3]), "r"(b0), "r"(b1));
}
__device__ __forceinline__ void ldsm4(unsigned& r0, unsigned& r1, unsigned& r2,
                                      unsigned& r3, unsigned addr) {
    asm volatile("ldmatrix.sync.aligned.m8n8.x4.shared.b16 {%0,%1,%2,%3}, [%4];"
                 : "=r"(r0), "=r"(r1), "=r"(r2), "=r"(r3) : "r"(addr));
}
__device__ __forceinline__ void ldsm4t(unsigned& r0, unsigned& r1, unsigned& r2,
                                       unsigned& r3, unsigned addr) {
    asm volatile("ldmatrix.sync.aligned.m8n8.x4.trans.shared.b16 {%0,%1,%2,%3}, [%4];"
                 : "=r"(r0), "=r"(r1), "=r"(r2), "=r"(r3) : "r"(addr));
}
__device__ __forceinline__ void cp16(unsigned s, const void* g) {
    asm volatile("cp.async.cg.shared.global [%0], [%1], 16;" :: "r"(s), "l"(g));
}
__device__ __forceinline__ void cp_commit() { asm volatile("cp.async.commit_group;"); }

// ---------------- convert kernels: f32 -> fp16 (RNE) ----------------
__global__ __launch_bounds__(256) void conv3(
    const float* __restrict__ a, const float* __restrict__ b, const float* __restrict__ c,
    __half* __restrict__ oa, __half* __restrict__ ob, __half* __restrict__ oc, int n4)
{
    const float* x = blockIdx.y == 0 ? a : blockIdx.y == 1 ? b : c;
    __half*      y = blockIdx.y == 0 ? oa : blockIdx.y == 1 ? ob : oc;
    int i = blockIdx.x * blockDim.x + threadIdx.x;
    if (i < n4) {
        float4 v = ((const float4*)x)[i];
        ((__half2*)y)[2 * i]     = __floats2half2_rn(v.x, v.y);
        ((__half2*)y)[2 * i + 1] = __floats2half2_rn(v.z, v.w);
    }
}
__global__ __launch_bounds__(256) void conv4(
    const float* __restrict__ a, const float* __restrict__ b,
    const float* __restrict__ c, const float* __restrict__ d,
    __half* __restrict__ oa, __half* __restrict__ ob,
    __half* __restrict__ oc, __half* __restrict__ od, int n4)
{
    const float* x = blockIdx.y == 0 ? a : blockIdx.y == 1 ? b : blockIdx.y == 2 ? c : d;
    __half*      y = blockIdx.y == 0 ? oa : blockIdx.y == 1 ? ob : blockIdx.y == 2 ? oc : od;
    int i = blockIdx.x * blockDim.x + threadIdx.x;
    if (i < n4) {
        float4 v = ((const float4*)x)[i];
        ((__half2*)y)[2 * i]     = __floats2half2_rn(v.x, v.y);
        ((__half2*)y)[2 * i + 1] = __floats2half2_rn(v.z, v.w);
    }
}

// ================= GEMM: C = (A @ W^T + bias) * osc, fp16 HMMA, 3-stage =================
#define GBM 128
#define GBN 128
#define GBK 64
#define HSR 72   // smem row stride in halves: 144B = 9x16B -> LDSM conflict-free
#define GBUF (2 * GBM * HSR)                 // halves per stage (A + W)
#define GEMM_SMEM (3 * GBUF * 2)             // 3-stage, bytes

template <bool HALF_OUT>
__global__ __launch_bounds__(256) void gemm_h(
    const __half* __restrict__ A0, const __half* __restrict__ A1,
    const __half* __restrict__ A2,
    const __half* __restrict__ W0, const __half* __restrict__ W1,
    const __half* __restrict__ W2,
    const float* __restrict__ B0, const float* __restrict__ B1,
    const float* __restrict__ B2,
    void* __restrict__ C0, void* __restrict__ C1, void* __restrict__ C2,
    float s0_, float s1_, float s2_)
{
    extern __shared__ __half smh[];
    const unsigned sS = (unsigned)__cvta_generic_to_shared(smh);

    const int z = blockIdx.z;
    const __half* A  = z == 0 ? A0 : z == 1 ? A1 : A2;
    const __half* W  = z == 0 ? W0 : z == 1 ? W1 : W2;
    const float* bias = z == 0 ? B0 : z == 1 ? B1 : B2;
    void* Cv = z == 0 ? C0 : z == 1 ? C1 : C2;
    const float osc = z == 0 ? s0_ : z == 1 ? s1_ : s2_;

    const int t = threadIdx.x, lane = t & 31, wid = t >> 5;
    const int wm = (wid >> 2) * 64;
    const int wn = (wid & 3) * 32;
    const int c4 = lane & 3, g = lane >> 2, lrow = lane & 7;
    const int rA = ((lane >> 3) & 1) * 8 + lrow;  const int kA = (lane >> 4) * 8;
    const int rB = ((lane >> 4) & 1) * 8 + lrow;  const int kB = ((lane >> 3) & 1) * 8;
    const int bm = blockIdx.y * GBM, bn = blockIdx.x * GBN;

    const int srow = t >> 3;
    const int scol = (t & 7) * 8;

    float acc[4][4][4];
#pragma unroll
    for (int mt = 0; mt < 4; mt++)
#pragma unroll
        for (int nt = 0; nt < 4; nt++)
#pragma unroll
            for (int i = 0; i < 4; i++) acc[mt][nt][i] = 0.f;

    auto issue = [&](int kt, int b) {
        int k0 = kt * GBK;
        unsigned sbuf = sS + (unsigned)(b * GBUF) * 2;
#pragma unroll
        for (int r = 0; r < 4; r++) {
            int row = srow + r * 32;
            cp16(sbuf + (unsigned)(row * HSR + scol) * 2,
                 A + (size_t)(bm + row) * DIM + k0 + scol);
            cp16(sbuf + (unsigned)(GBM * HSR + row * HSR + scol) * 2,
                 W + (size_t)(bn + row) * DIM + k0 + scol);
        }
        cp_commit();
    };

    const int NT = DIM / GBK;   // 16
    issue(0, 0); issue(1, 1);

    for (int kt = 0; kt < NT; kt++) {
        const int b = kt % 3;
        if (kt < NT - 1) asm volatile("cp.async.wait_group 1;");
        else             asm volatile("cp.async.wait_group 0;");
        __syncthreads();
        if (kt + 2 < NT) issue(kt + 2, (kt + 2) % 3);

        const unsigned abase = sS + (unsigned)(b * GBUF + (wm + rA) * HSR + kA) * 2;
        const unsigned bbase = sS + (unsigned)(b * GBUF + GBM * HSR + (wn + rB) * HSR + kB) * 2;

#pragma unroll
        for (int ks = 0; ks < 4; ks++) {
            unsigned af[4][4], bf[2][4];
#pragma unroll
            for (int mt = 0; mt < 4; mt++)
                ldsm4(af[mt][0], af[mt][1], af[mt][2], af[mt][3],
                      abase + (unsigned)(mt * 16 * HSR) * 2 + ks * 32);
#pragma unroll
            for (int ntp = 0; ntp < 2; ntp++)
                ldsm4(bf[ntp][0], bf[ntp][1], bf[ntp][2], bf[ntp][3],
                      bbase + (unsigned)(ntp * 16 * HSR) * 2 + ks * 32);
#pragma unroll
            for (int mt = 0; mt < 4; mt++)
#pragma unroll
                for (int ntp = 0; ntp < 2; ntp++) {
                    mma16(acc[mt][2 * ntp],     af[mt], bf[ntp][0], bf[ntp][1]);
                    mma16(acc[mt][2 * ntp + 1], af[mt], bf[ntp][2], bf[ntp][3]);
                }
        }
        __syncthreads();
    }

#pragma unroll
    for (int mt = 0; mt < 4; mt++) {
        int row = bm + wm + mt * 16 + g;
#pragma unroll
        for (int nt = 0; nt < 4; nt++) {
            int col = bn + wn + nt * 8 + 2 * c4;
            float b0 = __ldg(&bias[col]);
            float b1 = __ldg(&bias[col + 1]);
            float v00 = (acc[mt][nt][0] + b0) * osc, v01 = (acc[mt][nt][1] + b1) * osc;
            float v10 = (acc[mt][nt][2] + b0) * osc, v11 = (acc[mt][nt][3] + b1) * osc;
            if (HALF_OUT) {
                __half* C = (__half*)Cv;
                *(__half2*)&C[(size_t)row * DIM + col]       = __floats2half2_rn(v00, v01);
                *(__half2*)&C[(size_t)(row + 8) * DIM + col] = __floats2half2_rn(v10, v11);
            } else {
                float* C = (float*)Cv;
                *(float2*)&C[(size_t)row * DIM + col]       = make_float2(v00, v01);
                *(float2*)&C[(size_t)(row + 8) * DIM + col] = make_float2(v10, v11);
            }
        }
    }
}

// ================= flash attention, fp16 HMMA, log2-domain softmax =================
// Qp is pre-scaled by SCALE*log2e; softmax uses raw ex2, no guards (underflow -> 0).
#define KV_TILE (64 * HSR)
#define PS_OFF  (4 * KV_TILE)
#define MSK_OFF ((4 * KV_TILE + 128 * HSR) * 2)
#define ATT_SMEM (MSK_OFF + 2 * 64 * 4)

__global__ __launch_bounds__(256) void attn_h(
    const __half* __restrict__ Qp, const __half* __restrict__ Kp,
    const __half* __restrict__ Vp, const int* __restrict__ kv_mask,
    __half* __restrict__ Ao)
{
    extern __shared__ __half smh[];
    __half* Ks = smh;
    __half* Vs = smh + 2 * KV_TILE;
    __half* Ps = smh + PS_OFF;
    int*   Msm = (int*)((char*)smh + MSK_OFF);

    const unsigned sK = (unsigned)__cvta_generic_to_shared(Ks);
    const unsigned sV = (unsigned)__cvta_generic_to_shared(Vs);
    const unsigned sP = (unsigned)__cvta_generic_to_shared(Ps);
    const unsigned sM = (unsigned)__cvta_generic_to_shared(Msm);

    const int t = threadIdx.x, lane = t & 31, w = t >> 5;
    const int c4 = lane & 3, g = lane >> 2, lrow = lane & 7;
    const int rA = lane & 15;                     const int kA = (lane >> 4) * 8;
    const int rB = ((lane >> 4) & 1) * 8 + lrow;  const int kB = ((lane >> 3) & 1) * 8;
    const int rV = ((lane >> 3) & 1) * 8 + lrow;  const int dV = (lane >> 4) * 8;
    const int qt = blockIdx.x, h = blockIdx.y, b = blockIdx.z;

    const __half* Qb = Qp + ((size_t)(b * LQ + qt * 128)) * DIM + h * HD;
    const __half* Kb = Kp + (size_t)b * LK * DIM + h * HD;
    const __half* Vb = Vp + (size_t)b * LK * DIM + h * HD;
    const int*    mb = kv_mask + b * LK;

    auto issue_kv = [&](int kt, int buf) {
        const __half* Kg = Kb + (size_t)(kt * 64) * DIM;
        const __half* Vg = Vb + (size_t)(kt * 64) * DIM;
        int row0 = t >> 3, ch = (t & 7) * 8;
#pragma unroll
        for (int r = 0; r < 2; r++) {
            int row = row0 + r * 32;
            cp16(sK + (unsigned)(buf * KV_TILE + row * HSR + ch) * 2,
                 Kg + (size_t)row * DIM + ch);
            cp16(sV + (unsigned)(buf * KV_TILE + row * HSR + ch) * 2,
                 Vg + (size_t)row * DIM + ch);
        }
        if (t < 16) cp16(sM + buf * 256 + t * 16, mb + kt * 64 + t * 4);
        cp_commit();
    };

    issue_kv(0, 0);

    // stage Q (already pre-scaled) into Ps
    {
        int row0 = t >> 3, ch = (t & 7) * 8;
#pragma unroll
        for (int r = 0; r < 4; r++) {
            int row = row0 + r * 32;
            *(uint4*)&Ps[row * HSR + ch] = *(const uint4*)(Qb + (size_t)row * DIM + ch);
        }
    }
    __syncthreads();

    unsigned qf[4][4];
    {
        unsigned qbase = sP + (unsigned)((16 * w + rA) * HSR + kA) * 2;
#pragma unroll
        for (int ks = 0; ks < 4; ks++)
            ldsm4(qf[ks][0], qf[ks][1], qf[ks][2], qf[ks][3], qbase + ks * 32);
    }

    float O[8][4];
#pragma unroll
    for (int nt = 0; nt < 8; nt++)
#pragma unroll
        for (int i = 0; i < 4; i++) O[nt][i] = 0.f;
    float mr0 = -1e30f, mr1 = -1e30f, lr0 = 0.f, lr1 = 0.f;

    for (int kt = 0; kt < LK / 64; kt++) {
        asm volatile("cp.async.wait_group 0;");
        __syncthreads();
        if (kt + 1 < LK / 64) issue_kv(kt + 1, (kt + 1) & 1);

        const int buf = kt & 1;
        const int* Mc = Msm + buf * 64;
        const unsigned kbase = sK + (unsigned)(buf * KV_TILE + rB * HSR + kB) * 2;
        const unsigned vbase = sV + (unsigned)(buf * KV_TILE + rV * HSR + dV) * 2;

        // S = Q K^T (log2-domain scores)
        float S[8][4];
#pragma unroll
        for (int nt = 0; nt < 8; nt++)
#pragma unroll
            for (int i = 0; i < 4; i++) S[nt][i] = 0.f;

#pragma unroll
        for (int ks = 0; ks < 4; ks++) {
#pragma unroll
            for (int ntp = 0; ntp < 4; ntp++) {
                unsigned b0, b1, b2, b3;
                ldsm4(b0, b1, b2, b3, kbase + (unsigned)(ntp * 16 * HSR) * 2 + ks * 32);
                mma16(S[2 * ntp],     qf[ks], b0, b1);
                mma16(S[2 * ntp + 1], qf[ks], b2, b3);
            }
        }

        // mask: set to -1e30 (ex2 underflows to 0 later, no per-element guard)
#pragma unroll
        for (int nt = 0; nt < 8; nt++) {
            if (!Mc[nt * 8 + 2 * c4])     { S[nt][0] = -1e30f; S[nt][2] = -1e30f; }
            if (!Mc[nt * 8 + 2 * c4 + 1]) { S[nt][1] = -1e30f; S[nt][3] = -1e30f; }
        }

        // online softmax, log2 domain
        float mx0 = -1e30f, mx1 = -1e30f;
#pragma unroll
        for (int nt = 0; nt < 8; nt++) {
            mx0 = fmaxf(mx0, fmaxf(S[nt][0], S[nt][1]));
            mx1 = fmaxf(mx1, fmaxf(S[nt][2], S[nt][3]));
        }
        mx0 = fmaxf(mx0, __shfl_xor_sync(0xffffffffu, mx0, 1));
        mx0 = fmaxf(mx0, __shfl_xor_sync(0xffffffffu, mx0, 2));
        mx1 = fmaxf(mx1, __shfl_xor_sync(0xffffffffu, mx1, 1));
        mx1 = fmaxf(mx1, __shfl_xor_sync(0xffffffffu, mx1, 2));

        float mn0 = fmaxf(mr0, mx0), mn1 = fmaxf(mr1, mx1);
        float a0 = ex2(mr0 - mn0), a1 = ex2(mr1 - mn1);
        mr0 = mn0; mr1 = mn1; lr0 *= a0; lr1 *= a1;

        float s0 = 0.f, s1 = 0.f;
#pragma unroll
        for (int nt = 0; nt < 8; nt++) {
            O[nt][0] *= a0; O[nt][1] *= a0; O[nt][2] *= a1; O[nt][3] *= a1;
            float p0 = ex2(S[nt][0] - mn0);
            float p1 = ex2(S[nt][1] - mn0);
            float p2 = ex2(S[nt][2] - mn1);
            float p3 = ex2(S[nt][3] - mn1);
            S[nt][0] = p0; S[nt][1] = p1; S[nt][2] = p2; S[nt][3] = p3;
            s0 += p0 + p1; s1 += p2 + p3;
        }
        s0 += __shfl_xor_sync(0xffffffffu, s0, 1);
        s0 += __shfl_xor_sync(0xffffffffu, s0, 2);
        s1 += __shfl_xor_sync(0xffffffffu, s1, 1);
        s1 += __shfl_xor_sync(0xffffffffu, s1, 2);
        lr0 += s0; lr1 += s1;

        // O += P @ V : P stays in registers (S C-frag == P A-frag)
#pragma unroll
        for (int kk = 0; kk < 4; kk++) {
            unsigned pa[4];
            __half2 h0 = __floats2half2_rn(S[2 * kk][0],     S[2 * kk][1]);
            __half2 h1 = __floats2half2_rn(S[2 * kk][2],     S[2 * kk][3]);
            __half2 h2 = __floats2half2_rn(S[2 * kk + 1][0], S[2 * kk + 1][1]);
            __half2 h3 = __floats2half2_rn(S[2 * kk + 1][2], S[2 * kk + 1][3]);
            pa[0] = *(unsigned*)&h0; pa[1] = *(unsigned*)&h1;
            pa[2] = *(unsigned*)&h2; pa[3] = *(unsigned*)&h3;
#pragma unroll
            for (int ntp = 0; ntp < 4; ntp++) {
                unsigned v0, v1, v2, v3;
                ldsm4t(v0, v1, v2, v3,
                       vbase + (unsigned)(kk * 16 * HSR) * 2 + ntp * 32);
                mma16(O[2 * ntp],     pa, v0, v1);
                mma16(O[2 * ntp + 1], pa, v2, v3);
            }
        }
    }

    // epilogue: normalize, store fp16 for the final GEMM
    float inv0 = 1.f / lr0, inv1 = 1.f / lr1;
    __half* Ob = Ao + ((size_t)(b * LQ + qt * 128)) * DIM + h * HD;
    int row0 = 16 * w + g;
#pragma unroll
    for (int nt = 0; nt < 8; nt++) {
        int col = nt * 8 + 2 * c4;
        *(__half2*)&Ob[(size_t)row0 * DIM + col] =
            __floats2half2_rn(O[nt][0] * inv0, O[nt][1] * inv0);
        *(__half2*)&Ob[(size_t)(row0 + 8) * DIM + col] =
            __floats2half2_rn(O[nt][2] * inv1, O[nt][3] * inv1);
    }
}

// ---------------- launch ----------------
extern "C" void kernel_launch(void* const* d_in, const int* in_sizes, int n_in,
                              void* d_out, int out_size)
{
    const float* q       = (const float*)d_in[0];
    const float* k       = (const float*)d_in[1];
    const float* v       = (const float*)d_in[2];
    const int*   kv_mask = (const int*)d_in[3];
    const float* Wq      = (const float*)d_in[4];
    const float* bq      = (const float*)d_in[5];
    const float* Wk      = (const float*)d_in[6];
    const float* bk      = (const float*)d_in[7];
    const float* Wv      = (const float*)d_in[8];
    const float* bv      = (const float*)d_in[9];
    const float* Wo      = (const float*)d_in[10];
    const float* bo      = (const float*)d_in[11];
    float* out = (float*)d_out;

    __half *qh, *kh, *vh, *wq, *wk, *wv, *wo, *Qp, *Kp, *Vp, *Ao;
    cudaGetSymbolAddress((void**)&qh, g_qh);
    cudaGetSymbolAddress((void**)&kh, g_kh);
    cudaGetSymbolAddress((void**)&vh, g_vh);
    cudaGetSymbolAddress((void**)&wq, g_wq);
    cudaGetSymbolAddress((void**)&wk, g_wk);
    cudaGetSymbolAddress((void**)&wv, g_wv);
    cudaGetSymbolAddress((void**)&wo, g_wo);
    cudaGetSymbolAddress((void**)&Qp, g_Qp);
    cudaGetSymbolAddress((void**)&Kp, g_Kp);
    cudaGetSymbolAddress((void**)&Vp, g_Vp);
    cudaGetSymbolAddress((void**)&Ao, g_Ao);

    cudaFuncSetAttribute(gemm_h<true>,  cudaFuncAttributeMaxDynamicSharedMemorySize, GEMM_SMEM);
    cudaFuncSetAttribute(gemm_h<false>, cudaFuncAttributeMaxDynamicSharedMemorySize, GEMM_SMEM);
    cudaFuncSetAttribute(attn_h, cudaFuncAttributeMaxDynamicSharedMemorySize, ATT_SMEM);

    const int ACT4 = BATCH * LQ * DIM / 4;
    const int W4   = DIM * DIM / 4;
    conv3<<<dim3(ACT4 / 256, 3), 256>>>(q, k, v, qh, kh, vh, ACT4);
    conv4<<<dim3(W4 / 256, 4), 256>>>(Wq, Wk, Wv, Wo, wq, wk, wv, wo, W4);

    // merged Q/K/V projections; Q output pre-scaled by SCALE*log2e
    gemm_h<true><<<dim3(DIM / GBN, (BATCH * LQ) / GBM, 3), 256, GEMM_SMEM>>>(
        qh, kh, vh, wq, wk, wv, bq, bk, bv, Qp, Kp, Vp,
        QSCALE, 1.0f, 1.0f);

    attn_h<<<dim3(LQ / 128, NH, BATCH), 256, ATT_SMEM>>>(Qp, Kp, Vp, kv_mask, Ao);

    // output projection, fp32 out
    gemm_h<false><<<dim3(DIM / GBN, (BATCH * LQ) / GBM, 1), 256, GEMM_SMEM>>>(
        Ao, Ao, Ao, wo, wo, wo, bo, bo, bo, out, out, out,
        1.0f, 1.0f, 1.0f);
}